// round 11
// baseline (speedup 1.0000x reference)
#include <cuda_runtime.h>
#include <cuda_fp16.h>
#include <cstdint>
#include <cstddef>

#define BB   4
#define CC   256
#define NN   4096
#define GG   32
#define CPG  8
#define EPSV 1e-5f

#define TBM 128
#define TBN 128
#define TBK 32            // halves per k-chunk (2 x k16 MMA steps)
#define SKH 40            // K-major smem row stride in halves (80B)
#define SKB 136           // BTRANS smem row stride in halves (272B)
#define STAGES 4
#define TILE_A (TBM * SKH * 2)            // 10240 B
#define TILE_B0 (TBN * SKH * 2)           // 10240 B (B K-major)
#define TILE_B1 (TBK * SKB * 2)           // 8704 B  (B k-row-major, trans)

// ---------------- scratch (device globals) ----------------------------------
__device__ __half g_wqkvh[768 * CC];             // rows 0-255 wq/4, 256-511 wk/4, 512-767 wv
__device__ __half g_woh [CC * CC];
__device__ float  g_bqkv[768];                   // bq/4, bk/4, bv
__device__ __half g_hn  [(size_t)BB * NN * CC];  // [b][n][c]
__device__ __half g_qkv [(size_t)BB * NN * 768]; // [b][n][768]
__device__ __half g_eS  [(size_t)BB * NN * NN];  // expS [b][nq][nk]
__device__ __half g_at  [(size_t)BB * NN * CC];  // attn [b][nq][c] (normalized)
__device__ float  g_mean[BB * GG];
__device__ float  g_rstd[BB * GG];

// ---------------- helpers ----------------------------------------------------
__device__ __forceinline__ void mma_f16(float* c, const uint32_t* a, uint32_t b0, uint32_t b1)
{
    asm volatile(
        "mma.sync.aligned.m16n8k16.row.col.f32.f16.f16.f32 "
        "{%0,%1,%2,%3},{%4,%5,%6,%7},{%8,%9},{%0,%1,%2,%3};\n"
        : "+f"(c[0]), "+f"(c[1]), "+f"(c[2]), "+f"(c[3])
        : "r"(a[0]), "r"(a[1]), "r"(a[2]), "r"(a[3]), "r"(b0), "r"(b1));
}
__device__ __forceinline__ void ldsm_x4(uint32_t* r, uint32_t addr)
{
    asm volatile("ldmatrix.sync.aligned.m8n8.x4.shared.b16 {%0,%1,%2,%3}, [%4];"
                 : "=r"(r[0]), "=r"(r[1]), "=r"(r[2]), "=r"(r[3]) : "r"(addr));
}
__device__ __forceinline__ void ldsm_x4_t(uint32_t* r, uint32_t addr)
{
    asm volatile("ldmatrix.sync.aligned.m8n8.x4.trans.shared.b16 {%0,%1,%2,%3}, [%4];"
                 : "=r"(r[0]), "=r"(r[1]), "=r"(r[2]), "=r"(r[3]) : "r"(addr));
}
__device__ __forceinline__ void cp_async16(void* smem_dst, const void* gptr)
{
    uint32_t s = (uint32_t)__cvta_generic_to_shared(smem_dst);
    asm volatile("cp.async.cg.shared.global [%0], [%1], 16;\n" :: "r"(s), "l"(gptr));
}
__device__ __forceinline__ void cp_commit() { asm volatile("cp.async.commit_group;\n"); }
template <int Nw>
__device__ __forceinline__ void cp_wait() { asm volatile("cp.async.wait_group %0;\n" :: "n"(Nw)); }

// ---------------- fused prep (weights->half) + groupnorm stats ---------------
#define PREP_BLOCKS 1027
__global__ void prep_and_stats(const float* __restrict__ wq, const float* __restrict__ wk,
                               const float* __restrict__ wv, const float* __restrict__ wo,
                               const float* __restrict__ bq, const float* __restrict__ bk,
                               const float* __restrict__ bv, const float* __restrict__ x)
{
    if (blockIdx.x < PREP_BLOCKS) {
        int i = blockIdx.x * 256 + threadIdx.x;
        if (i < 196608) {                          // wqkv [768][256]
            int r = i >> 8;
            float v;
            if (r < 256)      v = wq[i] * 0.25f;
            else if (r < 512) v = wk[i - 65536] * 0.25f;
            else              v = wv[i - 131072];
            g_wqkvh[i] = __float2half(v);
        } else if (i < 262144) {
            g_woh[i - 196608] = __float2half(wo[i - 196608]);
        } else if (i < 262912) {
            int j = i - 262144;
            float v;
            if (j < 256)      v = bq[j] * 0.25f;
            else if (j < 512) v = bk[j - 256] * 0.25f;
            else              v = bv[j - 512];
            g_bqkv[j] = v;
        }
        return;
    }
    // groupnorm stats
    int bg = blockIdx.x - PREP_BLOCKS;
    const float* xs = x + (size_t)bg * (CPG * NN);
    float s = 0.f, s2 = 0.f;
    for (int i = threadIdx.x; i < CPG * NN; i += 256) {
        float v = xs[i];
        s += v; s2 += v * v;
    }
    __shared__ float rs[512];
    rs[threadIdx.x] = s; rs[256 + threadIdx.x] = s2;
    __syncthreads();
    for (int off = 128; off > 0; off >>= 1) {
        if (threadIdx.x < off) {
            rs[threadIdx.x]       += rs[threadIdx.x + off];
            rs[256 + threadIdx.x] += rs[256 + threadIdx.x + off];
        }
        __syncthreads();
    }
    if (threadIdx.x == 0) {
        float mean = rs[0] * (1.f / (CPG * NN));
        float var  = rs[256] * (1.f / (CPG * NN)) - mean * mean;
        g_mean[bg] = mean;
        g_rstd[bg] = rsqrtf(var + EPSV);
    }
}

// x[b][c][n] -> hn[b][n][c] (half). block (32,8), grid (NN/32, CC/32, BB)
__global__ void gn_transpose(const float* __restrict__ x,
                             const float* __restrict__ gamma, const float* __restrict__ beta)
{
    __shared__ float tile[32][33];
    int b = blockIdx.z;
    int n0 = blockIdx.x * 32, c0 = blockIdx.y * 32;
    int tx = threadIdx.x, ty = threadIdx.y;
    const float* xb = x + (size_t)b * CC * NN;
#pragma unroll
    for (int j = 0; j < 4; j++) {
        int c = c0 + ty + j * 8;
        float mean = g_mean[b * GG + (c >> 3)];
        float rstd = g_rstd[b * GG + (c >> 3)];
        float ga = gamma[c] * rstd;
        float be = beta[c] - mean * ga;
        tile[ty + j * 8][tx] = xb[(size_t)c * NN + n0 + tx] * ga + be;
    }
    __syncthreads();
    __half* hb = g_hn + (size_t)b * NN * CC;
#pragma unroll
    for (int j = 0; j < 4; j++) {
        int n = n0 + ty + j * 8;
        hb[(size_t)n * CC + c0 + tx] = __float2half(tile[tx][ty + j * 8]);
    }
}

// ---------------- fp16 TC GEMM (128x128, 2 CTA/SM) ---------------------------
// BTRANS=0: B stored [n][k] K-major.  BTRANS=1: B stored [k][n] (trans ldmatrix).
// RSUM=1: accumulate fp32 row sums of A fragments (for in-kernel softmax norm).
// mode 0: half out, + bias_col[n]
// mode 1: half out = exp(acc)
// mode 2: half out = acc / rowsum(A)          (requires RSUM=1)
// mode 3: fp32 out = acc + bias_row[m] + residual
template <int BTRANS, int RSUM>
__global__ void __launch_bounds__(256, 2)
hgemm(const __half* __restrict__ A, int ldA, size_t sA,
      const __half* __restrict__ B, int ldB, size_t sB,
      void* __restrict__ Cv, int ldC, size_t sC,
      int M, int K,
      const float* __restrict__ bias_row, const float* __restrict__ bias_col,
      const float* __restrict__ residual, int mode)
{
    constexpr int TILE_Bx = BTRANS ? TILE_B1 : TILE_B0;
    constexpr int STAGE_B = TILE_A + TILE_Bx;

    const int b  = blockIdx.z;
    const int m0 = blockIdx.y * TBM;
    const int n0 = blockIdx.x * TBN;

    extern __shared__ char smem[];

    const int tid  = threadIdx.x;
    const int lane = tid & 31;
    const int wid  = tid >> 5;
    const int wm   = wid >> 2;
    const int wn   = wid & 3;
    const int g    = lane >> 2;
    const int th4  = lane & 3;
    const int mi   = lane >> 3;
    const int ri   = lane & 7;

    const __half* Ap = A + (size_t)b * sA + (size_t)m0 * ldA;
    const __half* Bp = BTRANS ? (B + (size_t)b * sB + n0)
                              : (B + (size_t)b * sB + (size_t)n0 * ldB);

    const uint32_t su = (uint32_t)__cvta_generic_to_shared(smem);

    float acc[4][4][4];
#pragma unroll
    for (int i = 0; i < 4; i++)
#pragma unroll
        for (int j = 0; j < 4; j++)
#pragma unroll
            for (int r = 0; r < 4; r++) acc[i][j][r] = 0.f;

    float rsum[8];
    if (RSUM) {
#pragma unroll
        for (int i = 0; i < 8; i++) rsum[i] = 0.f;
    }

    const int T = K / TBK;
    const int crow = tid >> 2;        // 0..63
    const int c4   = tid & 3;

    auto load_tile = [&](int st, int t) {
        char* sa = smem + st * STAGE_B;
        char* sb = sa + TILE_A;
        const __half* Ag = Ap + (size_t)t * TBK;
#pragma unroll
        for (int j = 0; j < 2; j++) {
            int row = crow + j * 64;
            cp_async16(sa + row * (SKH * 2) + c4 * 16, Ag + (size_t)row * ldA + c4 * 8);
        }
        if (BTRANS) {
            const __half* Bg = Bp + (size_t)t * TBK * ldB;
#pragma unroll
            for (int j = 0; j < 2; j++) {
                int slot = tid + j * 256;
                int row = slot >> 4, col = slot & 15;
                cp_async16(sb + row * (SKB * 2) + col * 16, Bg + (size_t)row * ldB + col * 8);
            }
        } else {
            const __half* Bg = Bp + (size_t)t * TBK;
#pragma unroll
            for (int j = 0; j < 2; j++) {
                int row = crow + j * 64;
                cp_async16(sb + row * (SKH * 2) + c4 * 16, Bg + (size_t)row * ldB + c4 * 8);
            }
        }
    };

#pragma unroll
    for (int t = 0; t < STAGES - 1; t++) {
        if (t < T) load_tile(t, t);
        cp_commit();
    }

    for (int t = 0; t < T; t++) {
        cp_wait<STAGES - 2>();
        __syncthreads();

        int tl = t + STAGES - 1;
        if (tl < T) load_tile(tl % STAGES, tl);
        cp_commit();

        const int slot = t % STAGES;
        const uint32_t a_base = su + slot * STAGE_B;
        const uint32_t b_base = a_base + TILE_A;

        if (RSUM) {
            // single-phase loads (register headroom for rsum)
#pragma unroll
            for (int ph = 0; ph < 2; ph++) {
                const int kk = ph * 16;
                uint32_t av[4][4], bv[2][4];
#pragma unroll
                for (int mt = 0; mt < 4; mt++) {
                    int row = wm * 64 + mt * 16 + ((mi & 1) << 3) + ri;
                    int col = kk + ((mi & 2) << 2);
                    ldsm_x4(av[mt], a_base + (row * SKH + col) * 2);
                }
                if (BTRANS) {
#pragma unroll
                    for (int p = 0; p < 2; p++) {
                        int krow = kk + ((mi & 1) << 3) + ri;
                        int col  = wn * 32 + p * 16 + ((mi >> 1) << 3);
                        ldsm_x4_t(bv[p], b_base + (krow * SKB + col) * 2);
                    }
                } else {
#pragma unroll
                    for (int p = 0; p < 2; p++) {
                        int row = wn * 32 + p * 16 + ((mi >> 1) << 3) + ri;
                        int col = kk + ((mi & 1) << 3);
                        ldsm_x4(bv[p], b_base + (row * SKH + col) * 2);
                    }
                }
#pragma unroll
                for (int mt = 0; mt < 4; mt++)
#pragma unroll
                    for (int nt = 0; nt < 4; nt++)
                        mma_f16(acc[mt][nt], av[mt],
                                bv[nt >> 1][(nt & 1) * 2], bv[nt >> 1][(nt & 1) * 2 + 1]);
                // row sums of this A phase (fp16 pair-adds, fp32 accumulate)
#pragma unroll
                for (int mt = 0; mt < 4; mt++) {
                    __half2 u0 = __hadd2(*(__half2*)&av[mt][0], *(__half2*)&av[mt][2]); // row g
                    __half2 u1 = __hadd2(*(__half2*)&av[mt][1], *(__half2*)&av[mt][3]); // row g+8
                    float2 f0 = __half22float2(u0);
                    float2 f1 = __half22float2(u1);
                    rsum[mt * 2]     += f0.x + f0.y;
                    rsum[mt * 2 + 1] += f1.x + f1.y;
                }
            }
        } else {
            // two-phase prefetch (R10 pattern)
            uint32_t av[2][4][4], bv[2][2][4];
#pragma unroll
            for (int ph = 0; ph < 2; ph++) {
                const int kk = ph * 16;
#pragma unroll
                for (int mt = 0; mt < 4; mt++) {
                    int row = wm * 64 + mt * 16 + ((mi & 1) << 3) + ri;
                    int col = kk + ((mi & 2) << 2);
                    ldsm_x4(av[ph][mt], a_base + (row * SKH + col) * 2);
                }
#pragma unroll
                for (int p = 0; p < 2; p++) {
                    int row = wn * 32 + p * 16 + ((mi >> 1) << 3) + ri;
                    int col = kk + ((mi & 1) << 3);
                    ldsm_x4(bv[ph][p], b_base + (row * SKH + col) * 2);
                }
            }
#pragma unroll
            for (int ph = 0; ph < 2; ph++)
#pragma unroll
                for (int mt = 0; mt < 4; mt++)
#pragma unroll
                    for (int nt = 0; nt < 4; nt++)
                        mma_f16(acc[mt][nt], av[ph][mt],
                                bv[ph][nt >> 1][(nt & 1) * 2], bv[ph][nt >> 1][(nt & 1) * 2 + 1]);
        }
    }

    if (RSUM) {
        // complete row sums across the th4 lane group (lanes share rows via g)
#pragma unroll
        for (int i = 0; i < 8; i++) {
            rsum[i] += __shfl_xor_sync(0xffffffffu, rsum[i], 1);
            rsum[i] += __shfl_xor_sync(0xffffffffu, rsum[i], 2);
        }
    }

    // ---------------- epilogues ----------------
    if (mode == 1) {
        __half* C = (__half*)Cv + (size_t)b * sC;
#pragma unroll
        for (int mt = 0; mt < 4; mt++) {
#pragma unroll
            for (int nt = 0; nt < 4; nt++) {
                int col = n0 + wn * 32 + nt * 8 + 2 * th4;
#pragma unroll
                for (int h = 0; h < 2; h++) {
                    int row = m0 + wm * 64 + mt * 16 + g + 8 * h;
                    float e0 = __expf(acc[mt][nt][2 * h]);
                    float e1 = __expf(acc[mt][nt][2 * h + 1]);
                    *(__half2*)(C + (size_t)row * ldC + col) = __floats2half2_rn(e0, e1);
                }
            }
        }
        return;
    }

    if (mode == 3) {
        float* C = (float*)Cv + (size_t)b * sC;
        const float* R = residual + (size_t)b * sC;
#pragma unroll
        for (int mt = 0; mt < 4; mt++) {
#pragma unroll
            for (int nt = 0; nt < 4; nt++) {
                int col = n0 + wn * 32 + nt * 8 + 2 * th4;
#pragma unroll
                for (int h = 0; h < 2; h++) {
                    int row = m0 + wm * 64 + mt * 16 + g + 8 * h;
                    float br = bias_row[row];
                    float2 rv = *(const float2*)(R + (size_t)row * ldC + col);
                    float2 o;
                    o.x = acc[mt][nt][2 * h]     + br + rv.x;
                    o.y = acc[mt][nt][2 * h + 1] + br + rv.y;
                    *(float2*)(C + (size_t)row * ldC + col) = o;
                }
            }
        }
        return;
    }

    __half* C = (__half*)Cv + (size_t)b * sC;
#pragma unroll
    for (int mt = 0; mt < 4; mt++) {
#pragma unroll
        for (int nt = 0; nt < 4; nt++) {
            int col = n0 + wn * 32 + nt * 8 + 2 * th4;
            float bc0 = bias_col ? bias_col[col]     : 0.f;
            float bc1 = bias_col ? bias_col[col + 1] : 0.f;
#pragma unroll
            for (int h = 0; h < 2; h++) {
                int row = m0 + wm * 64 + mt * 16 + g + 8 * h;
                float o0 = acc[mt][nt][2 * h];
                float o1 = acc[mt][nt][2 * h + 1];
                if (RSUM && mode == 2) {
                    float sc = 1.f / rsum[mt * 2 + h];
                    o0 *= sc; o1 *= sc;
                } else {
                    o0 += bc0; o1 += bc1;
                }
                *(__half2*)(C + (size_t)row * ldC + col) = __floats2half2_rn(o0, o1);
            }
        }
    }
}

// ---------------- launch -----------------------------------------------------
extern "C" void kernel_launch(void* const* d_in, const int* in_sizes, int n_in,
                              void* d_out, int out_size)
{
    const float* x     = (const float*)d_in[0];
    const float* gamma = (const float*)d_in[1];
    const float* beta  = (const float*)d_in[2];
    const float* wq    = (const float*)d_in[3];
    const float* bq    = (const float*)d_in[4];
    const float* wk    = (const float*)d_in[5];
    const float* bk    = (const float*)d_in[6];
    const float* wv    = (const float*)d_in[7];
    const float* bv    = (const float*)d_in[8];
    const float* wo    = (const float*)d_in[9];
    const float* bo    = (const float*)d_in[10];
    float* out = (float*)d_out;

    __half *wqkvh, *woh, *hn, *qkv, *eS, *at;
    float *bqkv;
    cudaGetSymbolAddress((void**)&wqkvh, g_wqkvh);
    cudaGetSymbolAddress((void**)&woh,   g_woh);
    cudaGetSymbolAddress((void**)&bqkv,  g_bqkv);
    cudaGetSymbolAddress((void**)&hn,    g_hn);
    cudaGetSymbolAddress((void**)&qkv,   g_qkv);
    cudaGetSymbolAddress((void**)&eS,    g_eS);
    cudaGetSymbolAddress((void**)&at,    g_at);

    constexpr int SMEM0 = STAGES * (TILE_A + TILE_B0);
    constexpr int SMEM1 = STAGES * (TILE_A + TILE_B1);

    static bool attr_set = false;
    if (!attr_set) {
        cudaFuncSetAttribute(hgemm<0,0>, cudaFuncAttributeMaxDynamicSharedMemorySize, SMEM0);
        cudaFuncSetAttribute(hgemm<1,1>, cudaFuncAttributeMaxDynamicSharedMemorySize, SMEM1);
        attr_set = true;
    }

    prep_and_stats<<<PREP_BLOCKS + BB * GG, 256>>>(wq, wk, wv, wo, bq, bk, bv, x);
    gn_transpose<<<dim3(NN / 32, CC / 32, BB), dim3(32, 8)>>>(x, gamma, beta);

    // qkv[n][768] = hn[n][c] x wqkv[d][c]^T + bqkv
    hgemm<0,0><<<dim3(768 / TBN, NN / TBM, BB), 256, SMEM0>>>(
        hn, CC, (size_t)NN * CC, wqkvh, CC, 0,
        qkv, 768, (size_t)NN * 768, NN, CC,
        nullptr, bqkv, nullptr, 0);

    // expS[nq][nk] = exp(q . k)
    hgemm<0,0><<<dim3(NN / TBN, NN / TBM, BB), 256, SMEM0>>>(
        qkv, 768, (size_t)NN * 768, qkv + 256, 768, (size_t)NN * 768,
        eS, NN, (size_t)NN * NN, NN, CC,
        nullptr, nullptr, nullptr, 1);

    // attn[nq][c] = (expS[nq][nk] x v[nk][c]) / rowsum(expS)   (in-kernel norm)
    hgemm<1,1><<<dim3(CC / TBN, NN / TBM, BB), 256, SMEM1>>>(
        eS, NN, (size_t)NN * NN, qkv + 512, 768, (size_t)NN * 768,
        at, CC, (size_t)NN * CC, NN, NN,
        nullptr, nullptr, nullptr, 2);

    // out[c][n] = wo[c][k] x attn[n][k]^T + bo[c] + x[c][n]   (fp32)
    hgemm<0,0><<<dim3(NN / TBN, CC / TBM, BB), 256, SMEM0>>>(
        woh, CC, 0, at, CC, (size_t)NN * CC,
        out, NN, (size_t)CC * NN, CC, CC,
        bo, nullptr, x, 3);
}

// round 12
// speedup vs baseline: 1.1346x; 1.1346x over previous
#include <cuda_runtime.h>
#include <cuda_fp16.h>
#include <cstdint>
#include <cstddef>

#define BB   4
#define CC   256
#define NN   4096
#define GG   32
#define CPG  8
#define EPSV 1e-5f

#define TBM 128
#define TBN 128
#define TBK 32
#define SKH 40            // K-major smem row stride in halves (80B)
#define STAGES 4
#define TILE_A (TBM * SKH * 2)            // 10240 B
#define TILE_B0 (TBN * SKH * 2)           // 10240 B

// fused-attention smem layout (dynamic)
#define QK_STAGE_B (2 * 10240)            // Q chunk + K chunk
#define P_OFF   (4 * QK_STAGE_B)          // 81920
#define P_STRIDE 136                       // halves (272B)
#define V_OFF   (P_OFF + 128 * P_STRIDE * 2)      // 81920 + 34816 = 116736
#define V_STRIDE 264                       // halves (528B)
#define FUSED_SMEM (V_OFF + 128 * V_STRIDE * 2)   // 184320

// ---------------- scratch (device globals) ----------------------------------
__device__ __half g_wqkvh[768 * CC];             // rows 0-255 wq/4, 256-511 wk/4, 512-767 wv
__device__ __half g_woh [CC * CC];
__device__ float  g_bqkv[768];
__device__ __half g_hn  [(size_t)BB * NN * CC];  // [b][n][c]
__device__ __half g_qkv [(size_t)BB * NN * 768]; // [b][n][768]
__device__ __half g_at  [(size_t)BB * NN * CC];  // attn [b][nq][c] (normalized)
__device__ float  g_mean[BB * GG];
__device__ float  g_rstd[BB * GG];

// ---------------- helpers ----------------------------------------------------
__device__ __forceinline__ void mma_f16(float* c, const uint32_t* a, uint32_t b0, uint32_t b1)
{
    asm volatile(
        "mma.sync.aligned.m16n8k16.row.col.f32.f16.f16.f32 "
        "{%0,%1,%2,%3},{%4,%5,%6,%7},{%8,%9},{%0,%1,%2,%3};\n"
        : "+f"(c[0]), "+f"(c[1]), "+f"(c[2]), "+f"(c[3])
        : "r"(a[0]), "r"(a[1]), "r"(a[2]), "r"(a[3]), "r"(b0), "r"(b1));
}
__device__ __forceinline__ void ldsm_x4(uint32_t* r, uint32_t addr)
{
    asm volatile("ldmatrix.sync.aligned.m8n8.x4.shared.b16 {%0,%1,%2,%3}, [%4];"
                 : "=r"(r[0]), "=r"(r[1]), "=r"(r[2]), "=r"(r[3]) : "r"(addr));
}
__device__ __forceinline__ void ldsm_x4_t(uint32_t* r, uint32_t addr)
{
    asm volatile("ldmatrix.sync.aligned.m8n8.x4.trans.shared.b16 {%0,%1,%2,%3}, [%4];"
                 : "=r"(r[0]), "=r"(r[1]), "=r"(r[2]), "=r"(r[3]) : "r"(addr));
}
__device__ __forceinline__ void cp_async16(void* smem_dst, const void* gptr)
{
    uint32_t s = (uint32_t)__cvta_generic_to_shared(smem_dst);
    asm volatile("cp.async.cg.shared.global [%0], [%1], 16;\n" :: "r"(s), "l"(gptr));
}
__device__ __forceinline__ void cp_commit() { asm volatile("cp.async.commit_group;\n"); }
template <int Nw>
__device__ __forceinline__ void cp_wait() { asm volatile("cp.async.wait_group %0;\n" :: "n"(Nw)); }

// ---------------- fused prep (weights->half) + groupnorm stats ---------------
#define PREP_BLOCKS 1027
__global__ void prep_and_stats(const float* __restrict__ wq, const float* __restrict__ wk,
                               const float* __restrict__ wv, const float* __restrict__ wo,
                               const float* __restrict__ bq, const float* __restrict__ bk,
                               const float* __restrict__ bv, const float* __restrict__ x)
{
    if (blockIdx.x < PREP_BLOCKS) {
        int i = blockIdx.x * 256 + threadIdx.x;
        if (i < 196608) {
            int r = i >> 8;
            float v;
            if (r < 256)      v = wq[i] * 0.25f;
            else if (r < 512) v = wk[i - 65536] * 0.25f;
            else              v = wv[i - 131072];
            g_wqkvh[i] = __float2half(v);
        } else if (i < 262144) {
            g_woh[i - 196608] = __float2half(wo[i - 196608]);
        } else if (i < 262912) {
            int j = i - 262144;
            float v;
            if (j < 256)      v = bq[j] * 0.25f;
            else if (j < 512) v = bk[j - 256] * 0.25f;
            else              v = bv[j - 512];
            g_bqkv[j] = v;
        }
        return;
    }
    int bg = blockIdx.x - PREP_BLOCKS;
    const float* xs = x + (size_t)bg * (CPG * NN);
    float s = 0.f, s2 = 0.f;
    for (int i = threadIdx.x; i < CPG * NN; i += 256) {
        float v = xs[i];
        s += v; s2 += v * v;
    }
    __shared__ float rs[512];
    rs[threadIdx.x] = s; rs[256 + threadIdx.x] = s2;
    __syncthreads();
    for (int off = 128; off > 0; off >>= 1) {
        if (threadIdx.x < off) {
            rs[threadIdx.x]       += rs[threadIdx.x + off];
            rs[256 + threadIdx.x] += rs[256 + threadIdx.x + off];
        }
        __syncthreads();
    }
    if (threadIdx.x == 0) {
        float mean = rs[0] * (1.f / (CPG * NN));
        float var  = rs[256] * (1.f / (CPG * NN)) - mean * mean;
        g_mean[bg] = mean;
        g_rstd[bg] = rsqrtf(var + EPSV);
    }
}

// x[b][c][n] -> hn[b][n][c] (half)
__global__ void gn_transpose(const float* __restrict__ x,
                             const float* __restrict__ gamma, const float* __restrict__ beta)
{
    __shared__ float tile[32][33];
    int b = blockIdx.z;
    int n0 = blockIdx.x * 32, c0 = blockIdx.y * 32;
    int tx = threadIdx.x, ty = threadIdx.y;
    const float* xb = x + (size_t)b * CC * NN;
#pragma unroll
    for (int j = 0; j < 4; j++) {
        int c = c0 + ty + j * 8;
        float mean = g_mean[b * GG + (c >> 3)];
        float rstd = g_rstd[b * GG + (c >> 3)];
        float ga = gamma[c] * rstd;
        float be = beta[c] - mean * ga;
        tile[ty + j * 8][tx] = xb[(size_t)c * NN + n0 + tx] * ga + be;
    }
    __syncthreads();
    __half* hb = g_hn + (size_t)b * NN * CC;
#pragma unroll
    for (int j = 0; j < 4; j++) {
        int n = n0 + ty + j * 8;
        hb[(size_t)n * CC + c0 + tx] = __float2half(tile[tx][ty + j * 8]);
    }
}

// ---------------- fp16 TC GEMM (R10 proven; modes 0 and 3 only) --------------
__global__ void __launch_bounds__(256, 2)
hgemm(const __half* __restrict__ A, int ldA, size_t sA,
      const __half* __restrict__ B, int ldB, size_t sB,
      void* __restrict__ Cv, int ldC, size_t sC,
      int K,
      const float* __restrict__ bias_row, const float* __restrict__ bias_col,
      const float* __restrict__ residual, int mode)
{
    constexpr int STAGE_B = TILE_A + TILE_B0;
    const int b  = blockIdx.z;
    const int m0 = blockIdx.y * TBM;
    const int n0 = blockIdx.x * TBN;

    extern __shared__ char smem[];

    const int tid  = threadIdx.x;
    const int lane = tid & 31;
    const int wid  = tid >> 5;
    const int wm   = wid >> 2;
    const int wn   = wid & 3;
    const int g    = lane >> 2;
    const int th4  = lane & 3;
    const int mi   = lane >> 3;
    const int ri   = lane & 7;

    const __half* Ap = A + (size_t)b * sA + (size_t)m0 * ldA;
    const __half* Bp = B + (size_t)b * sB + (size_t)n0 * ldB;
    const uint32_t su = (uint32_t)__cvta_generic_to_shared(smem);

    float acc[4][4][4];
#pragma unroll
    for (int i = 0; i < 4; i++)
#pragma unroll
        for (int j = 0; j < 4; j++)
#pragma unroll
            for (int r = 0; r < 4; r++) acc[i][j][r] = 0.f;

    const int T = K / TBK;
    const int crow = tid >> 2;
    const int c4   = tid & 3;

    auto load_tile = [&](int st, int t) {
        char* sa = smem + st * STAGE_B;
        char* sb = sa + TILE_A;
        const __half* Ag = Ap + (size_t)t * TBK;
        const __half* Bg = Bp + (size_t)t * TBK;
#pragma unroll
        for (int j = 0; j < 2; j++) {
            int row = crow + j * 64;
            cp_async16(sa + row * (SKH * 2) + c4 * 16, Ag + (size_t)row * ldA + c4 * 8);
            cp_async16(sb + row * (SKH * 2) + c4 * 16, Bg + (size_t)row * ldB + c4 * 8);
        }
    };

#pragma unroll
    for (int t = 0; t < STAGES - 1; t++) {
        if (t < T) load_tile(t, t);
        cp_commit();
    }

    for (int t = 0; t < T; t++) {
        cp_wait<STAGES - 2>();
        __syncthreads();
        int tl = t + STAGES - 1;
        if (tl < T) load_tile(tl % STAGES, tl);
        cp_commit();

        const int slot = t % STAGES;
        const uint32_t a_base = su + slot * STAGE_B;
        const uint32_t b_base = a_base + TILE_A;

        uint32_t av[2][4][4], bv[2][2][4];
#pragma unroll
        for (int ph = 0; ph < 2; ph++) {
            const int kk = ph * 16;
#pragma unroll
            for (int mt = 0; mt < 4; mt++) {
                int row = wm * 64 + mt * 16 + ((mi & 1) << 3) + ri;
                int col = kk + ((mi & 2) << 2);
                ldsm_x4(av[ph][mt], a_base + (row * SKH + col) * 2);
            }
#pragma unroll
            for (int p = 0; p < 2; p++) {
                int row = wn * 32 + p * 16 + ((mi >> 1) << 3) + ri;
                int col = kk + ((mi & 1) << 3);
                ldsm_x4(bv[ph][p], b_base + (row * SKH + col) * 2);
            }
        }
#pragma unroll
        for (int ph = 0; ph < 2; ph++)
#pragma unroll
            for (int mt = 0; mt < 4; mt++)
#pragma unroll
                for (int nt = 0; nt < 4; nt++)
                    mma_f16(acc[mt][nt], av[ph][mt],
                            bv[ph][nt >> 1][(nt & 1) * 2], bv[ph][nt >> 1][(nt & 1) * 2 + 1]);
    }

    if (mode == 3) {
        float* C = (float*)Cv + (size_t)b * sC;
        const float* R = residual + (size_t)b * sC;
#pragma unroll
        for (int mt = 0; mt < 4; mt++) {
#pragma unroll
            for (int nt = 0; nt < 4; nt++) {
                int col = n0 + wn * 32 + nt * 8 + 2 * th4;
#pragma unroll
                for (int h = 0; h < 2; h++) {
                    int row = m0 + wm * 64 + mt * 16 + g + 8 * h;
                    float br = bias_row[row];
                    float2 rv = *(const float2*)(R + (size_t)row * ldC + col);
                    float2 o;
                    o.x = acc[mt][nt][2 * h]     + br + rv.x;
                    o.y = acc[mt][nt][2 * h + 1] + br + rv.y;
                    *(float2*)(C + (size_t)row * ldC + col) = o;
                }
            }
        }
        return;
    }

    __half* C = (__half*)Cv + (size_t)b * sC;
#pragma unroll
    for (int mt = 0; mt < 4; mt++) {
#pragma unroll
        for (int nt = 0; nt < 4; nt++) {
            int col = n0 + wn * 32 + nt * 8 + 2 * th4;
            float bc0 = bias_col ? bias_col[col]     : 0.f;
            float bc1 = bias_col ? bias_col[col + 1] : 0.f;
#pragma unroll
            for (int h = 0; h < 2; h++) {
                int row = m0 + wm * 64 + mt * 16 + g + 8 * h;
                *(__half2*)(C + (size_t)row * ldC + col) =
                    __floats2half2_rn(acc[mt][nt][2 * h] + bc0, acc[mt][nt][2 * h + 1] + bc1);
            }
        }
    }
}

// ---------------- fused attention: S=QK^T -> exp -> O += P V -----------------
// grid (NN/128, BB), 256 threads, 1 CTA/SM. Q,K,V from g_qkv; out -> g_at.
__global__ void __launch_bounds__(256, 1)
fused_attn()
{
    extern __shared__ char smem[];
    __shared__ float cs[4][128];
    __shared__ float invls[128];

    const int tid  = threadIdx.x;
    const int lane = tid & 31;
    const int wid  = tid >> 5;
    const int wm   = wid >> 2;        // 0..1
    const int wn   = wid & 3;         // 0..3
    const int g    = lane >> 2;
    const int th4  = lane & 3;
    const int mi   = lane >> 3;
    const int ri   = lane & 7;

    const int m0 = blockIdx.x * 128;
    const int b  = blockIdx.y;

    const __half* qkvb = g_qkv + (size_t)b * NN * 768;
    const __half* Qg = qkvb + (size_t)m0 * 768;          // q cols 0..255
    const uint32_t su = (uint32_t)__cvta_generic_to_shared(smem);

    const int crow = tid >> 2;        // 0..63
    const int c4   = tid & 3;

    float oacc[4][8][4];
#pragma unroll
    for (int i = 0; i < 4; i++)
#pragma unroll
        for (int j = 0; j < 8; j++)
#pragma unroll
            for (int r = 0; r < 4; r++) oacc[i][j][r] = 0.f;
    float rsum[8];
#pragma unroll
    for (int i = 0; i < 8; i++) rsum[i] = 0.f;

    // Q/K chunk loader: chunk c of key-tile jt into slot st
    auto load_qk = [&](int st, int jt, int c) {
        char* sq = smem + st * QK_STAGE_B;
        char* sk = sq + 10240;
        const __half* Qc = Qg + c * 32;
        const __half* Kc = qkvb + (size_t)jt * 128 * 768 + 256 + c * 32;
#pragma unroll
        for (int j = 0; j < 2; j++) {
            int row = crow + j * 64;
            cp_async16(sq + row * (SKH * 2) + c4 * 16, Qc + (size_t)row * 768 + c4 * 8);
            cp_async16(sk + row * (SKH * 2) + c4 * 16, Kc + (size_t)row * 768 + c4 * 8);
        }
    };
    auto load_v = [&](int jt) {
        char* sv = smem + V_OFF;
        const __half* Vg = qkvb + (size_t)jt * 128 * 768 + 512;
#pragma unroll
        for (int i = 0; i < 16; i++) {
            int slot = tid + i * 256;         // 0..4095
            int row = slot >> 5, cc = slot & 31;
            cp_async16(sv + row * (V_STRIDE * 2) + cc * 16, Vg + (size_t)row * 768 + cc * 8);
        }
    };

    for (int jt = 0; jt < NN / 128; jt++) {
        // prologue: 3 QK chunks, then V (kept out of the early wait window)
        load_qk(0, jt, 0); cp_commit();
        load_qk(1, jt, 1); cp_commit();
        load_qk(2, jt, 2); cp_commit();
        load_v(jt);        cp_commit();

        float sacc[4][4][4];
#pragma unroll
        for (int i = 0; i < 4; i++)
#pragma unroll
            for (int j = 0; j < 4; j++)
#pragma unroll
                for (int r = 0; r < 4; r++) sacc[i][j][r] = 0.f;

        // ---- S phase: 8 K-chunks ----
        for (int c = 0; c < 8; c++) {
            cp_wait<2>();
            __syncthreads();
            if (c + 3 < 8) load_qk((c + 3) & 3, jt, c + 3);
            cp_commit();

            const uint32_t q_base = su + (c & 3) * QK_STAGE_B;
            const uint32_t k_base = q_base + 10240;
#pragma unroll
            for (int ph = 0; ph < 2; ph++) {
                const int kk = ph * 16;
                uint32_t av[4][4], bv[2][4];
#pragma unroll
                for (int mt = 0; mt < 4; mt++) {
                    int row = wm * 64 + mt * 16 + ((mi & 1) << 3) + ri;
                    int col = kk + ((mi & 2) << 2);
                    ldsm_x4(av[mt], q_base + (row * SKH + col) * 2);
                }
#pragma unroll
                for (int p = 0; p < 2; p++) {
                    int row = wn * 32 + p * 16 + ((mi >> 1) << 3) + ri;
                    int col = kk + ((mi & 1) << 3);
                    ldsm_x4(bv[p], k_base + (row * SKH + col) * 2);
                }
#pragma unroll
                for (int mt = 0; mt < 4; mt++)
#pragma unroll
                    for (int nt = 0; nt < 4; nt++)
                        mma_f16(sacc[mt][nt], av[mt],
                                bv[nt >> 1][(nt & 1) * 2], bv[nt >> 1][(nt & 1) * 2 + 1]);
            }
        }

        cp_wait<0>();   // V complete; drain trailing empties

        // ---- exp -> P (smem) + row-sum partials ----
        {
            char* sp = smem + P_OFF;
#pragma unroll
            for (int mt = 0; mt < 4; mt++) {
#pragma unroll
                for (int nt = 0; nt < 4; nt++) {
                    int col = wn * 32 + nt * 8 + 2 * th4;
#pragma unroll
                    for (int h = 0; h < 2; h++) {
                        int row = wm * 64 + mt * 16 + g + 8 * h;
                        float e0 = __expf(sacc[mt][nt][2 * h]);
                        float e1 = __expf(sacc[mt][nt][2 * h + 1]);
                        rsum[mt * 2 + h] += e0 + e1;
                        *(__half2*)(sp + (row * P_STRIDE + col) * 2) = __floats2half2_rn(e0, e1);
                    }
                }
            }
        }
        __syncthreads();

        // ---- PV phase: O += P(128x128) x V(128keys x 256c) ----
        {
            const uint32_t p_base = su + P_OFF;
            const uint32_t v_base = su + V_OFF;
#pragma unroll
            for (int ks = 0; ks < 8; ks++) {
                uint32_t pa[4][4], vb[4][4];
#pragma unroll
                for (int mt = 0; mt < 4; mt++) {
                    int row = wm * 64 + mt * 16 + ((mi & 1) << 3) + ri;
                    int col = ks * 16 + ((mi & 2) << 2);
                    ldsm_x4(pa[mt], p_base + (row * P_STRIDE + col) * 2);
                }
#pragma unroll
                for (int p = 0; p < 4; p++) {
                    int krow = ks * 16 + ((mi & 1) << 3) + ri;
                    int colc = wn * 64 + p * 16 + ((mi >> 1) << 3);
                    ldsm_x4_t(vb[p], v_base + (krow * V_STRIDE + colc) * 2);
                }
#pragma unroll
                for (int mt = 0; mt < 4; mt++)
#pragma unroll
                    for (int nt = 0; nt < 8; nt++)
                        mma_f16(oacc[mt][nt], pa[mt],
                                vb[nt >> 1][(nt & 1) * 2], vb[nt >> 1][(nt & 1) * 2 + 1]);
            }
        }
        __syncthreads();
    }

    // ---- final row sums across wn warps, normalize, store ----
#pragma unroll
    for (int i = 0; i < 8; i++) {
        rsum[i] += __shfl_xor_sync(0xffffffffu, rsum[i], 1);
        rsum[i] += __shfl_xor_sync(0xffffffffu, rsum[i], 2);
    }
    if (th4 == 0) {
#pragma unroll
        for (int mt = 0; mt < 4; mt++)
#pragma unroll
            for (int h = 0; h < 2; h++)
                cs[wn][wm * 64 + mt * 16 + g + 8 * h] = rsum[mt * 2 + h];
    }
    __syncthreads();
    if (tid < 128)
        invls[tid] = 1.f / (cs[0][tid] + cs[1][tid] + cs[2][tid] + cs[3][tid]);
    __syncthreads();

    __half* Ob = g_at + ((size_t)b * NN + m0) * CC;
#pragma unroll
    for (int mt = 0; mt < 4; mt++) {
#pragma unroll
        for (int h = 0; h < 2; h++) {
            int row = wm * 64 + mt * 16 + g + 8 * h;
            float sc = invls[row];
#pragma unroll
            for (int nt = 0; nt < 8; nt++) {
                int col = wn * 64 + nt * 8 + 2 * th4;
                *(__half2*)(Ob + (size_t)row * CC + col) =
                    __floats2half2_rn(oacc[mt][nt][2 * h] * sc, oacc[mt][nt][2 * h + 1] * sc);
            }
        }
    }
}

// ---------------- launch -----------------------------------------------------
extern "C" void kernel_launch(void* const* d_in, const int* in_sizes, int n_in,
                              void* d_out, int out_size)
{
    const float* x     = (const float*)d_in[0];
    const float* gamma = (const float*)d_in[1];
    const float* beta  = (const float*)d_in[2];
    const float* wq    = (const float*)d_in[3];
    const float* bq    = (const float*)d_in[4];
    const float* wk    = (const float*)d_in[5];
    const float* bk    = (const float*)d_in[6];
    const float* wv    = (const float*)d_in[7];
    const float* bv    = (const float*)d_in[8];
    const float* wo    = (const float*)d_in[9];
    const float* bo    = (const float*)d_in[10];
    float* out = (float*)d_out;

    __half *wqkvh, *woh, *hn, *qkv, *at;
    float *bqkv;
    cudaGetSymbolAddress((void**)&wqkvh, g_wqkvh);
    cudaGetSymbolAddress((void**)&woh,   g_woh);
    cudaGetSymbolAddress((void**)&bqkv,  g_bqkv);
    cudaGetSymbolAddress((void**)&hn,    g_hn);
    cudaGetSymbolAddress((void**)&qkv,   g_qkv);
    cudaGetSymbolAddress((void**)&at,    g_at);

    constexpr int SMEM0 = STAGES * (TILE_A + TILE_B0);

    static bool attr_set = false;
    if (!attr_set) {
        cudaFuncSetAttribute(hgemm, cudaFuncAttributeMaxDynamicSharedMemorySize, SMEM0);
        cudaFuncSetAttribute(fused_attn, cudaFuncAttributeMaxDynamicSharedMemorySize, FUSED_SMEM);
        attr_set = true;
    }

    prep_and_stats<<<PREP_BLOCKS + BB * GG, 256>>>(wq, wk, wv, wo, bq, bk, bv, x);
    gn_transpose<<<dim3(NN / 32, CC / 32, BB), dim3(32, 8)>>>(x, gamma, beta);

    // qkv[n][768] = hn[n][c] x wqkv[d][c]^T + bqkv
    hgemm<<<dim3(768 / TBN, NN / TBM, BB), 256, SMEM0>>>(
        hn, CC, (size_t)NN * CC, wqkvh, CC, 0,
        qkv, 768, (size_t)NN * 768, CC,
        nullptr, bqkv, nullptr, 0);

    // attn = softmax(q k^T) v   (fused, normalized, half out)
    fused_attn<<<dim3(NN / 128, BB), 256, FUSED_SMEM>>>();

    // out[c][n] = wo[c][k] x attn[n][k]^T + bo[c] + x[c][n]   (fp32)
    hgemm<<<dim3(NN / TBN, CC / TBM, BB), 256, SMEM0>>>(
        woh, CC, 0, at, CC, (size_t)NN * CC,
        out, NN, (size_t)CC * NN, CC,
        bo, nullptr, x, 3);
}

// round 13
// speedup vs baseline: 1.1772x; 1.0376x over previous
#include <cuda_runtime.h>
#include <cuda_fp16.h>
#include <cstdint>
#include <cstddef>

#define BB   4
#define CC   256
#define NN   4096
#define GG   32
#define CPG  8
#define EPSV 1e-5f

#define TBM 128
#define TBN 128
#define TBK 32
#define SKH 40            // K-major smem row stride in halves (80B)
#define STAGES 4
#define TILE_A (TBM * SKH * 2)            // 10240 B
#define TILE_B0 (TBN * SKH * 2)           // 10240 B

// fused-attention smem layout (dynamic)
#define CHUNK_B 10240                      // one 128x32 panel (stride SKH)
#define Q_OFF   0                          // 8 chunks: 81920 B
#define K_OFF   (8 * CHUNK_B)              // 4 slots:  40960 B
#define P_OFF   (K_OFF + 4 * CHUNK_B)      // 122880
#define P_STRIDE 136                       // halves (272B)
#define V_OFF   (P_OFF + 128 * P_STRIDE * 2)      // 157696
#define V_STRIDE 264                       // halves (528B)
#define FUSED_SMEM (V_OFF + 128 * V_STRIDE * 2)   // 225280

// ---------------- scratch (device globals) ----------------------------------
__device__ __half g_wqkvh[768 * CC];             // rows 0-255 wq/4, 256-511 wk/4, 512-767 wv
__device__ __half g_woh [CC * CC];
__device__ float  g_bqkv[768];
__device__ __half g_hn  [(size_t)BB * NN * CC];  // [b][n][c]
__device__ __half g_qkv [(size_t)BB * NN * 768]; // [b][n][768]
__device__ __half g_at  [(size_t)BB * NN * CC];  // attn [b][nq][c] (normalized)
__device__ float  g_mean[BB * GG];
__device__ float  g_rstd[BB * GG];

// ---------------- helpers ----------------------------------------------------
__device__ __forceinline__ void mma_f16(float* c, const uint32_t* a, uint32_t b0, uint32_t b1)
{
    asm volatile(
        "mma.sync.aligned.m16n8k16.row.col.f32.f16.f16.f32 "
        "{%0,%1,%2,%3},{%4,%5,%6,%7},{%8,%9},{%0,%1,%2,%3};\n"
        : "+f"(c[0]), "+f"(c[1]), "+f"(c[2]), "+f"(c[3])
        : "r"(a[0]), "r"(a[1]), "r"(a[2]), "r"(a[3]), "r"(b0), "r"(b1));
}
__device__ __forceinline__ void ldsm_x4(uint32_t* r, uint32_t addr)
{
    asm volatile("ldmatrix.sync.aligned.m8n8.x4.shared.b16 {%0,%1,%2,%3}, [%4];"
                 : "=r"(r[0]), "=r"(r[1]), "=r"(r[2]), "=r"(r[3]) : "r"(addr));
}
__device__ __forceinline__ void ldsm_x4_t(uint32_t* r, uint32_t addr)
{
    asm volatile("ldmatrix.sync.aligned.m8n8.x4.trans.shared.b16 {%0,%1,%2,%3}, [%4];"
                 : "=r"(r[0]), "=r"(r[1]), "=r"(r[2]), "=r"(r[3]) : "r"(addr));
}
__device__ __forceinline__ void cp_async16(void* smem_dst, const void* gptr)
{
    uint32_t s = (uint32_t)__cvta_generic_to_shared(smem_dst);
    asm volatile("cp.async.cg.shared.global [%0], [%1], 16;\n" :: "r"(s), "l"(gptr));
}
__device__ __forceinline__ void cp_commit() { asm volatile("cp.async.commit_group;\n"); }
template <int Nw>
__device__ __forceinline__ void cp_wait() { asm volatile("cp.async.wait_group %0;\n" :: "n"(Nw)); }

// ---------------- fused prep (weights->half) + groupnorm stats ---------------
#define PREP_BLOCKS 1027
__global__ void prep_and_stats(const float* __restrict__ wq, const float* __restrict__ wk,
                               const float* __restrict__ wv, const float* __restrict__ wo,
                               const float* __restrict__ bq, const float* __restrict__ bk,
                               const float* __restrict__ bv, const float* __restrict__ x)
{
    if (blockIdx.x < PREP_BLOCKS) {
        int i = blockIdx.x * 256 + threadIdx.x;
        if (i < 196608) {
            int r = i >> 8;
            float v;
            if (r < 256)      v = wq[i] * 0.25f;
            else if (r < 512) v = wk[i - 65536] * 0.25f;
            else              v = wv[i - 131072];
            g_wqkvh[i] = __float2half(v);
        } else if (i < 262144) {
            g_woh[i - 196608] = __float2half(wo[i - 196608]);
        } else if (i < 262912) {
            int j = i - 262144;
            float v;
            if (j < 256)      v = bq[j] * 0.25f;
            else if (j < 512) v = bk[j - 256] * 0.25f;
            else              v = bv[j - 512];
            g_bqkv[j] = v;
        }
        return;
    }
    int bg = blockIdx.x - PREP_BLOCKS;
    const float* xs = x + (size_t)bg * (CPG * NN);
    float s = 0.f, s2 = 0.f;
    for (int i = threadIdx.x; i < CPG * NN; i += 256) {
        float v = xs[i];
        s += v; s2 += v * v;
    }
    __shared__ float rs[512];
    rs[threadIdx.x] = s; rs[256 + threadIdx.x] = s2;
    __syncthreads();
    for (int off = 128; off > 0; off >>= 1) {
        if (threadIdx.x < off) {
            rs[threadIdx.x]       += rs[threadIdx.x + off];
            rs[256 + threadIdx.x] += rs[256 + threadIdx.x + off];
        }
        __syncthreads();
    }
    if (threadIdx.x == 0) {
        float mean = rs[0] * (1.f / (CPG * NN));
        float var  = rs[256] * (1.f / (CPG * NN)) - mean * mean;
        g_mean[bg] = mean;
        g_rstd[bg] = rsqrtf(var + EPSV);
    }
}

// x[b][c][n] -> hn[b][n][c] (half)
__global__ void gn_transpose(const float* __restrict__ x,
                             const float* __restrict__ gamma, const float* __restrict__ beta)
{
    __shared__ float tile[32][33];
    int b = blockIdx.z;
    int n0 = blockIdx.x * 32, c0 = blockIdx.y * 32;
    int tx = threadIdx.x, ty = threadIdx.y;
    const float* xb = x + (size_t)b * CC * NN;
#pragma unroll
    for (int j = 0; j < 4; j++) {
        int c = c0 + ty + j * 8;
        float mean = g_mean[b * GG + (c >> 3)];
        float rstd = g_rstd[b * GG + (c >> 3)];
        float ga = gamma[c] * rstd;
        float be = beta[c] - mean * ga;
        tile[ty + j * 8][tx] = xb[(size_t)c * NN + n0 + tx] * ga + be;
    }
    __syncthreads();
    __half* hb = g_hn + (size_t)b * NN * CC;
#pragma unroll
    for (int j = 0; j < 4; j++) {
        int n = n0 + ty + j * 8;
        hb[(size_t)n * CC + c0 + tx] = __float2half(tile[tx][ty + j * 8]);
    }
}

// ---------------- fp16 TC GEMM (R10 proven; modes 0 and 3) -------------------
__global__ void __launch_bounds__(256, 2)
hgemm(const __half* __restrict__ A, int ldA, size_t sA,
      const __half* __restrict__ B, int ldB, size_t sB,
      void* __restrict__ Cv, int ldC, size_t sC,
      int K,
      const float* __restrict__ bias_row, const float* __restrict__ bias_col,
      const float* __restrict__ residual, int mode)
{
    constexpr int STAGE_B = TILE_A + TILE_B0;
    const int b  = blockIdx.z;
    const int m0 = blockIdx.y * TBM;
    const int n0 = blockIdx.x * TBN;

    extern __shared__ char smem[];

    const int tid  = threadIdx.x;
    const int lane = tid & 31;
    const int wid  = tid >> 5;
    const int wm   = wid >> 2;
    const int wn   = wid & 3;
    const int g    = lane >> 2;
    const int th4  = lane & 3;
    const int mi   = lane >> 3;
    const int ri   = lane & 7;

    const __half* Ap = A + (size_t)b * sA + (size_t)m0 * ldA;
    const __half* Bp = B + (size_t)b * sB + (size_t)n0 * ldB;
    const uint32_t su = (uint32_t)__cvta_generic_to_shared(smem);

    float acc[4][4][4];
#pragma unroll
    for (int i = 0; i < 4; i++)
#pragma unroll
        for (int j = 0; j < 4; j++)
#pragma unroll
            for (int r = 0; r < 4; r++) acc[i][j][r] = 0.f;

    const int T = K / TBK;
    const int crow = tid >> 2;
    const int c4   = tid & 3;

    auto load_tile = [&](int st, int t) {
        char* sa = smem + st * STAGE_B;
        char* sb = sa + TILE_A;
        const __half* Ag = Ap + (size_t)t * TBK;
        const __half* Bg = Bp + (size_t)t * TBK;
#pragma unroll
        for (int j = 0; j < 2; j++) {
            int row = crow + j * 64;
            cp_async16(sa + row * (SKH * 2) + c4 * 16, Ag + (size_t)row * ldA + c4 * 8);
            cp_async16(sb + row * (SKH * 2) + c4 * 16, Bg + (size_t)row * ldB + c4 * 8);
        }
    };

#pragma unroll
    for (int t = 0; t < STAGES - 1; t++) {
        if (t < T) load_tile(t, t);
        cp_commit();
    }

    for (int t = 0; t < T; t++) {
        cp_wait<STAGES - 2>();
        __syncthreads();
        int tl = t + STAGES - 1;
        if (tl < T) load_tile(tl % STAGES, tl);
        cp_commit();

        const int slot = t % STAGES;
        const uint32_t a_base = su + slot * STAGE_B;
        const uint32_t b_base = a_base + TILE_A;

        uint32_t av[2][4][4], bv[2][2][4];
#pragma unroll
        for (int ph = 0; ph < 2; ph++) {
            const int kk = ph * 16;
#pragma unroll
            for (int mt = 0; mt < 4; mt++) {
                int row = wm * 64 + mt * 16 + ((mi & 1) << 3) + ri;
                int col = kk + ((mi & 2) << 2);
                ldsm_x4(av[ph][mt], a_base + (row * SKH + col) * 2);
            }
#pragma unroll
            for (int p = 0; p < 2; p++) {
                int row = wn * 32 + p * 16 + ((mi >> 1) << 3) + ri;
                int col = kk + ((mi & 1) << 3);
                ldsm_x4(bv[ph][p], b_base + (row * SKH + col) * 2);
            }
        }
#pragma unroll
        for (int ph = 0; ph < 2; ph++)
#pragma unroll
            for (int mt = 0; mt < 4; mt++)
#pragma unroll
                for (int nt = 0; nt < 4; nt++)
                    mma_f16(acc[mt][nt], av[ph][mt],
                            bv[ph][nt >> 1][(nt & 1) * 2], bv[ph][nt >> 1][(nt & 1) * 2 + 1]);
    }

    if (mode == 3) {
        float* C = (float*)Cv + (size_t)b * sC;
        const float* R = residual + (size_t)b * sC;
#pragma unroll
        for (int mt = 0; mt < 4; mt++) {
#pragma unroll
            for (int nt = 0; nt < 4; nt++) {
                int col = n0 + wn * 32 + nt * 8 + 2 * th4;
#pragma unroll
                for (int h = 0; h < 2; h++) {
                    int row = m0 + wm * 64 + mt * 16 + g + 8 * h;
                    float br = bias_row[row];
                    float2 rv = *(const float2*)(R + (size_t)row * ldC + col);
                    float2 o;
                    o.x = acc[mt][nt][2 * h]     + br + rv.x;
                    o.y = acc[mt][nt][2 * h + 1] + br + rv.y;
                    *(float2*)(C + (size_t)row * ldC + col) = o;
                }
            }
        }
        return;
    }

    __half* C = (__half*)Cv + (size_t)b * sC;
#pragma unroll
    for (int mt = 0; mt < 4; mt++) {
#pragma unroll
        for (int nt = 0; nt < 4; nt++) {
            int col = n0 + wn * 32 + nt * 8 + 2 * th4;
            float bc0 = bias_col ? bias_col[col]     : 0.f;
            float bc1 = bias_col ? bias_col[col + 1] : 0.f;
#pragma unroll
            for (int h = 0; h < 2; h++) {
                int row = m0 + wm * 64 + mt * 16 + g + 8 * h;
                *(__half2*)(C + (size_t)row * ldC + col) =
                    __floats2half2_rn(acc[mt][nt][2 * h] + bc0, acc[mt][nt][2 * h + 1] + bc1);
            }
        }
    }
}

// ---------------- fused attention: persistent Q + cross-tile pipeline --------
// grid (NN/128, BB), 256 threads, 1 CTA/SM.
// Commit-group order per tile j: [K0,K1,K2 (committed after S(j-1)), V(j)
// (after PV(j-1))], then one commit per S-chunk (loads K3..K7 for c<=4, empty
// for c>=5), then K0-2(j+1) after the S loop, V(j+1) after PV's barrier.
// Waits: chunk c<3 -> wait<3>; c>=3 -> wait<2> (also pins V(j)).
__global__ void __launch_bounds__(256, 1)
fused_attn()
{
    extern __shared__ char smem[];
    __shared__ float cs[4][128];
    __shared__ float invls[128];

    const int tid  = threadIdx.x;
    const int lane = tid & 31;
    const int wid  = tid >> 5;
    const int wm   = wid >> 2;        // 0..1
    const int wn   = wid & 3;         // 0..3
    const int g    = lane >> 2;
    const int th4  = lane & 3;
    const int mi   = lane >> 3;
    const int ri   = lane & 7;

    const int m0 = blockIdx.x * 128;
    const int b  = blockIdx.y;

    const __half* qkvb = g_qkv + (size_t)b * NN * 768;
    const __half* Qg = qkvb + (size_t)m0 * 768;          // q cols 0..255
    const uint32_t su = (uint32_t)__cvta_generic_to_shared(smem);

    const int crow = tid >> 2;        // 0..63
    const int c4   = tid & 3;

    float oacc[4][8][4];
#pragma unroll
    for (int i = 0; i < 4; i++)
#pragma unroll
        for (int j = 0; j < 8; j++)
#pragma unroll
            for (int r = 0; r < 4; r++) oacc[i][j][r] = 0.f;
    float rsum[8];
#pragma unroll
    for (int i = 0; i < 8; i++) rsum[i] = 0.f;

    // K chunk loader: chunk c of key-tile jt into slot st (guarded by jt range)
    auto load_k = [&](int st, int jt, int c) {
        if (jt >= NN / 128) return;
        char* sk = smem + K_OFF + st * CHUNK_B;
        const __half* Kc = qkvb + (size_t)jt * 128 * 768 + 256 + c * 32;
#pragma unroll
        for (int j = 0; j < 2; j++) {
            int row = crow + j * 64;
            cp_async16(sk + row * (SKH * 2) + c4 * 16, Kc + (size_t)row * 768 + c4 * 8);
        }
    };
    auto load_v = [&](int jt) {
        if (jt >= NN / 128) return;
        char* sv = smem + V_OFF;
        const __half* Vg = qkvb + (size_t)jt * 128 * 768 + 512;
#pragma unroll
        for (int i = 0; i < 16; i++) {
            int slot = tid + i * 256;         // 0..4095
            int row = slot >> 5, cc = slot & 31;
            cp_async16(sv + row * (V_STRIDE * 2) + cc * 16, Vg + (size_t)row * 768 + cc * 8);
        }
    };

    // ---- prologue: Q (persistent, one group), K0-2(0), V(0) ----
#pragma unroll
    for (int c = 0; c < 8; c++) {
        char* sq = smem + Q_OFF + c * CHUNK_B;
        const __half* Qc = Qg + c * 32;
#pragma unroll
        for (int j = 0; j < 2; j++) {
            int row = crow + j * 64;
            cp_async16(sq + row * (SKH * 2) + c4 * 16, Qc + (size_t)row * 768 + c4 * 8);
        }
    }
    cp_commit();
    load_k(0, 0, 0); cp_commit();
    load_k(1, 0, 1); cp_commit();
    load_k(2, 0, 2); cp_commit();
    load_v(0);       cp_commit();

    for (int jt = 0; jt < NN / 128; jt++) {
        float sacc[4][4][4];
#pragma unroll
        for (int i = 0; i < 4; i++)
#pragma unroll
            for (int j = 0; j < 4; j++)
#pragma unroll
                for (int r = 0; r < 4; r++) sacc[i][j][r] = 0.f;

        // ---- S phase: 8 K-chunks ----
#pragma unroll 1
        for (int c = 0; c < 8; c++) {
            if (c < 3) cp_wait<3>(); else cp_wait<2>();
            __syncthreads();
            load_k((c + 3) & 3, jt, c + 3);   // no-op (empty group) for c>=5
            cp_commit();

            const uint32_t q_base = su + Q_OFF + c * CHUNK_B;
            const uint32_t k_base = su + K_OFF + (c & 3) * CHUNK_B;
#pragma unroll
            for (int ph = 0; ph < 2; ph++) {
                const int kk = ph * 16;
                uint32_t av[4][4], bv[2][4];
#pragma unroll
                for (int mt = 0; mt < 4; mt++) {
                    int row = wm * 64 + mt * 16 + ((mi & 1) << 3) + ri;
                    int col = kk + ((mi & 2) << 2);
                    ldsm_x4(av[mt], q_base + (row * SKH + col) * 2);
                }
#pragma unroll
                for (int p = 0; p < 2; p++) {
                    int row = wn * 32 + p * 16 + ((mi >> 1) << 3) + ri;
                    int col = kk + ((mi & 1) << 3);
                    ldsm_x4(bv[p], k_base + (row * SKH + col) * 2);
                }
#pragma unroll
                for (int mt = 0; mt < 4; mt++)
#pragma unroll
                    for (int nt = 0; nt < 4; nt++)
                        mma_f16(sacc[mt][nt], av[mt],
                                bv[nt >> 1][(nt & 1) * 2], bv[nt >> 1][(nt & 1) * 2 + 1]);
            }
        }

        // prefetch next tile's first K chunks (slots 0-2 are dead by barriers)
        load_k(0, jt + 1, 0); cp_commit();
        load_k(1, jt + 1, 1); cp_commit();
        load_k(2, jt + 1, 2); cp_commit();

        // ---- exp -> P (smem) + row-sum partials (V(jt) pinned by c>=3 waits)
        {
            char* sp = smem + P_OFF;
#pragma unroll
            for (int mt = 0; mt < 4; mt++) {
#pragma unroll
                for (int nt = 0; nt < 4; nt++) {
                    int col = wn * 32 + nt * 8 + 2 * th4;
#pragma unroll
                    for (int h = 0; h < 2; h++) {
                        int row = wm * 64 + mt * 16 + g + 8 * h;
                        float e0 = __expf(sacc[mt][nt][2 * h]);
                        float e1 = __expf(sacc[mt][nt][2 * h + 1]);
                        rsum[mt * 2 + h] += e0 + e1;
                        *(__half2*)(sp + (row * P_STRIDE + col) * 2) = __floats2half2_rn(e0, e1);
                    }
                }
            }
        }
        __syncthreads();

        // ---- PV phase: O += P(128x128) x V(128keys x 256c) ----
        {
            const uint32_t p_base = su + P_OFF;
            const uint32_t v_base = su + V_OFF;
#pragma unroll
            for (int ks = 0; ks < 8; ks++) {
                uint32_t pa[4][4], vb[4][4];
#pragma unroll
                for (int mt = 0; mt < 4; mt++) {
                    int row = wm * 64 + mt * 16 + ((mi & 1) << 3) + ri;
                    int col = ks * 16 + ((mi & 2) << 2);
                    ldsm_x4(pa[mt], p_base + (row * P_STRIDE + col) * 2);
                }
#pragma unroll
                for (int p = 0; p < 4; p++) {
                    int krow = ks * 16 + ((mi & 1) << 3) + ri;
                    int colc = wn * 64 + p * 16 + ((mi >> 1) << 3);
                    ldsm_x4_t(vb[p], v_base + (krow * V_STRIDE + colc) * 2);
                }
#pragma unroll
                for (int mt = 0; mt < 4; mt++)
#pragma unroll
                    for (int nt = 0; nt < 8; nt++)
                        mma_f16(oacc[mt][nt], pa[mt],
                                vb[nt >> 1][(nt & 1) * 2], vb[nt >> 1][(nt & 1) * 2 + 1]);
            }
        }
        __syncthreads();

        // V buffer free -> prefetch next tile's V under the next S phase
        load_v(jt + 1); cp_commit();
    }

    // ---- final row sums across wn warps, normalize, store ----
#pragma unroll
    for (int i = 0; i < 8; i++) {
        rsum[i] += __shfl_xor_sync(0xffffffffu, rsum[i], 1);
        rsum[i] += __shfl_xor_sync(0xffffffffu, rsum[i], 2);
    }
    if (th4 == 0) {
#pragma unroll
        for (int mt = 0; mt < 4; mt++)
#pragma unroll
            for (int h = 0; h < 2; h++)
                cs[wn][wm * 64 + mt * 16 + g + 8 * h] = rsum[mt * 2 + h];
    }
    __syncthreads();
    if (tid < 128)
        invls[tid] = 1.f / (cs[0][tid] + cs[1][tid] + cs[2][tid] + cs[3][tid]);
    __syncthreads();

    __half* Ob = g_at + ((size_t)b * NN + m0) * CC;
#pragma unroll
    for (int mt = 0; mt < 4; mt++) {
#pragma unroll
        for (int h = 0; h < 2; h++) {
            int row = wm * 64 + mt * 16 + g + 8 * h;
            float sc = invls[row];
#pragma unroll
            for (int nt = 0; nt < 8; nt++) {
                int col = wn * 64 + nt * 8 + 2 * th4;
                *(__half2*)(Ob + (size_t)row * CC + col) =
                    __floats2half2_rn(oacc[mt][nt][2 * h] * sc, oacc[mt][nt][2 * h + 1] * sc);
            }
        }
    }
}

// ---------------- launch -----------------------------------------------------
extern "C" void kernel_launch(void* const* d_in, const int* in_sizes, int n_in,
                              void* d_out, int out_size)
{
    const float* x     = (const float*)d_in[0];
    const float* gamma = (const float*)d_in[1];
    const float* beta  = (const float*)d_in[2];
    const float* wq    = (const float*)d_in[3];
    const float* bq    = (const float*)d_in[4];
    const float* wk    = (const float*)d_in[5];
    const float* bk    = (const float*)d_in[6];
    const float* wv    = (const float*)d_in[7];
    const float* bv    = (const float*)d_in[8];
    const float* wo    = (const float*)d_in[9];
    const float* bo    = (const float*)d_in[10];
    float* out = (float*)d_out;

    __half *wqkvh, *woh, *hn, *qkv, *at;
    float *bqkv;
    cudaGetSymbolAddress((void**)&wqkvh, g_wqkvh);
    cudaGetSymbolAddress((void**)&woh,   g_woh);
    cudaGetSymbolAddress((void**)&bqkv,  g_bqkv);
    cudaGetSymbolAddress((void**)&hn,    g_hn);
    cudaGetSymbolAddress((void**)&qkv,   g_qkv);
    cudaGetSymbolAddress((void**)&at,    g_at);

    constexpr int SMEM0 = STAGES * (TILE_A + TILE_B0);

    static bool attr_set = false;
    if (!attr_set) {
        cudaFuncSetAttribute(hgemm, cudaFuncAttributeMaxDynamicSharedMemorySize, SMEM0);
        cudaFuncSetAttribute(fused_attn, cudaFuncAttributeMaxDynamicSharedMemorySize, FUSED_SMEM);
        attr_set = true;
    }

    prep_and_stats<<<PREP_BLOCKS + BB * GG, 256>>>(wq, wk, wv, wo, bq, bk, bv, x);
    gn_transpose<<<dim3(NN / 32, CC / 32, BB), dim3(32, 8)>>>(x, gamma, beta);

    // qkv[n][768] = hn[n][c] x wqkv[d][c]^T + bqkv
    hgemm<<<dim3(768 / TBN, NN / TBM, BB), 256, SMEM0>>>(
        hn, CC, (size_t)NN * CC, wqkvh, CC, 0,
        qkv, 768, (size_t)NN * 768, CC,
        nullptr, bqkv, nullptr, 0);

    // attn = softmax(q k^T) v   (fused, normalized, half out)
    fused_attn<<<dim3(NN / 128, BB), 256, FUSED_SMEM>>>();

    // out[c][n] = wo[c][k] x attn[n][k]^T + bo[c] + x[c][n]   (fp32)
    hgemm<<<dim3(NN / TBN, CC / TBM, BB), 256, SMEM0>>>(
        woh, CC, 0, at, CC, (size_t)NN * CC,
        out, NN, (size_t)CC * NN, CC,
        bo, nullptr, x, 3);
}

// round 15
// speedup vs baseline: 1.1847x; 1.0064x over previous
#include <cuda_runtime.h>
#include <cuda_fp16.h>
#include <cstdint>
#include <cstddef>

#define BB   4
#define CC   256
#define NN   4096
#define GG   32
#define CPG  8
#define EPSV 1e-5f

#define TBM 128
#define TBN 128
#define TBK 32
#define SKH 40            // K-major smem row stride in halves (80B)
#define STAGES 4
#define TILE_A (TBM * SKH * 2)            // 10240 B
#define TILE_B0 (TBN * SKH * 2)           // 10240 B

// fused-attention smem layout (dynamic)
#define CHUNK_B 10240                      // one 128x32 panel (stride SKH)
#define Q_OFF   0                          // 8 chunks: 81920 B
#define K_OFF   (8 * CHUNK_B)              // 4 slots:  40960 B
#define V_OFF   (K_OFF + 4 * CHUNK_B)      // 122880
#define V_STRIDE 264                       // halves (528B)
#define FUSED_SMEM (V_OFF + 128 * V_STRIDE * 2)   // 190464

// ---------------- scratch (device globals) ----------------------------------
__device__ __half g_wqkvh[768 * CC];             // rows 0-255 wq/4, 256-511 wk/4, 512-767 wv
__device__ __half g_woh [CC * CC];
__device__ float  g_bqkv[768];
__device__ __half g_hn  [(size_t)BB * NN * CC];  // [b][n][c]
__device__ __half g_qkv [(size_t)BB * NN * 768]; // [b][n][768]
__device__ __half g_at  [(size_t)BB * NN * CC];  // attn [b][nq][c] (normalized)
__device__ float  g_mean[BB * GG];
__device__ float  g_rstd[BB * GG];

// ---------------- helpers ----------------------------------------------------
__device__ __forceinline__ uint32_t f2h2(float a, float b)
{
    __half2 h = __floats2half2_rn(a, b);
    return *reinterpret_cast<uint32_t*>(&h);
}
__device__ __forceinline__ void mma_f16(float* c, const uint32_t* a, uint32_t b0, uint32_t b1)
{
    asm volatile(
        "mma.sync.aligned.m16n8k16.row.col.f32.f16.f16.f32 "
        "{%0,%1,%2,%3},{%4,%5,%6,%7},{%8,%9},{%0,%1,%2,%3};\n"
        : "+f"(c[0]), "+f"(c[1]), "+f"(c[2]), "+f"(c[3])
        : "r"(a[0]), "r"(a[1]), "r"(a[2]), "r"(a[3]), "r"(b0), "r"(b1));
}
__device__ __forceinline__ void ldsm_x4(uint32_t* r, uint32_t addr)
{
    asm volatile("ldmatrix.sync.aligned.m8n8.x4.shared.b16 {%0,%1,%2,%3}, [%4];"
                 : "=r"(r[0]), "=r"(r[1]), "=r"(r[2]), "=r"(r[3]) : "r"(addr));
}
__device__ __forceinline__ void ldsm_x4_t(uint32_t* r, uint32_t addr)
{
    asm volatile("ldmatrix.sync.aligned.m8n8.x4.trans.shared.b16 {%0,%1,%2,%3}, [%4];"
                 : "=r"(r[0]), "=r"(r[1]), "=r"(r[2]), "=r"(r[3]) : "r"(addr));
}
__device__ __forceinline__ void cp_async16(void* smem_dst, const void* gptr)
{
    uint32_t s = (uint32_t)__cvta_generic_to_shared(smem_dst);
    asm volatile("cp.async.cg.shared.global [%0], [%1], 16;\n" :: "r"(s), "l"(gptr));
}
__device__ __forceinline__ void cp_commit() { asm volatile("cp.async.commit_group;\n"); }
template <int Nw>
__device__ __forceinline__ void cp_wait() { asm volatile("cp.async.wait_group %0;\n" :: "n"(Nw)); }

// ---------------- fused prep (weights->half) + groupnorm stats ---------------
#define PREP_BLOCKS 1027
__global__ void prep_and_stats(const float* __restrict__ wq, const float* __restrict__ wk,
                               const float* __restrict__ wv, const float* __restrict__ wo,
                               const float* __restrict__ bq, const float* __restrict__ bk,
                               const float* __restrict__ bv, const float* __restrict__ x)
{
    if (blockIdx.x < PREP_BLOCKS) {
        int i = blockIdx.x * 256 + threadIdx.x;
        if (i < 196608) {
            int r = i >> 8;
            float v;
            if (r < 256)      v = wq[i] * 0.25f;
            else if (r < 512) v = wk[i - 65536] * 0.25f;
            else              v = wv[i - 131072];
            g_wqkvh[i] = __float2half(v);
        } else if (i < 262144) {
            g_woh[i - 196608] = __float2half(wo[i - 196608]);
        } else if (i < 262912) {
            int j = i - 262144;
            float v;
            if (j < 256)      v = bq[j] * 0.25f;
            else if (j < 512) v = bk[j - 256] * 0.25f;
            else              v = bv[j - 512];
            g_bqkv[j] = v;
        }
        return;
    }
    int bg = blockIdx.x - PREP_BLOCKS;
    const float* xs = x + (size_t)bg * (CPG * NN);
    float s = 0.f, s2 = 0.f;
    for (int i = threadIdx.x; i < CPG * NN; i += 256) {
        float v = xs[i];
        s += v; s2 += v * v;
    }
    __shared__ float rs[512];
    rs[threadIdx.x] = s; rs[256 + threadIdx.x] = s2;
    __syncthreads();
    for (int off = 128; off > 0; off >>= 1) {
        if (threadIdx.x < off) {
            rs[threadIdx.x]       += rs[threadIdx.x + off];
            rs[256 + threadIdx.x] += rs[256 + threadIdx.x + off];
        }
        __syncthreads();
    }
    if (threadIdx.x == 0) {
        float mean = rs[0] * (1.f / (CPG * NN));
        float var  = rs[256] * (1.f / (CPG * NN)) - mean * mean;
        g_mean[bg] = mean;
        g_rstd[bg] = rsqrtf(var + EPSV);
    }
}

// x[b][c][n] -> hn[b][n][c] (half)
__global__ void gn_transpose(const float* __restrict__ x,
                             const float* __restrict__ gamma, const float* __restrict__ beta)
{
    __shared__ float tile[32][33];
    int b = blockIdx.z;
    int n0 = blockIdx.x * 32, c0 = blockIdx.y * 32;
    int tx = threadIdx.x, ty = threadIdx.y;
    const float* xb = x + (size_t)b * CC * NN;
#pragma unroll
    for (int j = 0; j < 4; j++) {
        int c = c0 + ty + j * 8;
        float mean = g_mean[b * GG + (c >> 3)];
        float rstd = g_rstd[b * GG + (c >> 3)];
        float ga = gamma[c] * rstd;
        float be = beta[c] - mean * ga;
        tile[ty + j * 8][tx] = xb[(size_t)c * NN + n0 + tx] * ga + be;
    }
    __syncthreads();
    __half* hb = g_hn + (size_t)b * NN * CC;
#pragma unroll
    for (int j = 0; j < 4; j++) {
        int n = n0 + ty + j * 8;
        hb[(size_t)n * CC + c0 + tx] = __float2half(tile[tx][ty + j * 8]);
    }
}

// ---------------- fp16 TC GEMM (R10 proven; modes 0 and 3) -------------------
__global__ void __launch_bounds__(256, 2)
hgemm(const __half* __restrict__ A, int ldA, size_t sA,
      const __half* __restrict__ B, int ldB, size_t sB,
      void* __restrict__ Cv, int ldC, size_t sC,
      int K,
      const float* __restrict__ bias_row, const float* __restrict__ bias_col,
      const float* __restrict__ residual, int mode)
{
    constexpr int STAGE_B = TILE_A + TILE_B0;
    const int b  = blockIdx.z;
    const int m0 = blockIdx.y * TBM;
    const int n0 = blockIdx.x * TBN;

    extern __shared__ char smem[];

    const int tid  = threadIdx.x;
    const int lane = tid & 31;
    const int wid  = tid >> 5;
    const int wm   = wid >> 2;
    const int wn   = wid & 3;
    const int g    = lane >> 2;
    const int th4  = lane & 3;
    const int mi   = lane >> 3;
    const int ri   = lane & 7;

    const __half* Ap = A + (size_t)b * sA + (size_t)m0 * ldA;
    const __half* Bp = B + (size_t)b * sB + (size_t)n0 * ldB;
    const uint32_t su = (uint32_t)__cvta_generic_to_shared(smem);

    float acc[4][4][4];
#pragma unroll
    for (int i = 0; i < 4; i++)
#pragma unroll
        for (int j = 0; j < 4; j++)
#pragma unroll
            for (int r = 0; r < 4; r++) acc[i][j][r] = 0.f;

    const int T = K / TBK;
    const int crow = tid >> 2;
    const int c4   = tid & 3;

    auto load_tile = [&](int st, int t) {
        char* sa = smem + st * STAGE_B;
        char* sb = sa + TILE_A;
        const __half* Ag = Ap + (size_t)t * TBK;
        const __half* Bg = Bp + (size_t)t * TBK;
#pragma unroll
        for (int j = 0; j < 2; j++) {
            int row = crow + j * 64;
            cp_async16(sa + row * (SKH * 2) + c4 * 16, Ag + (size_t)row * ldA + c4 * 8);
            cp_async16(sb + row * (SKH * 2) + c4 * 16, Bg + (size_t)row * ldB + c4 * 8);
        }
    };

#pragma unroll
    for (int t = 0; t < STAGES - 1; t++) {
        if (t < T) load_tile(t, t);
        cp_commit();
    }

    for (int t = 0; t < T; t++) {
        cp_wait<STAGES - 2>();
        __syncthreads();
        int tl = t + STAGES - 1;
        if (tl < T) load_tile(tl % STAGES, tl);
        cp_commit();

        const int slot = t % STAGES;
        const uint32_t a_base = su + slot * STAGE_B;
        const uint32_t b_base = a_base + TILE_A;

        uint32_t av[2][4][4], bv[2][2][4];
#pragma unroll
        for (int ph = 0; ph < 2; ph++) {
            const int kk = ph * 16;
#pragma unroll
            for (int mt = 0; mt < 4; mt++) {
                int row = wm * 64 + mt * 16 + ((mi & 1) << 3) + ri;
                int col = kk + ((mi & 2) << 2);
                ldsm_x4(av[ph][mt], a_base + (row * SKH + col) * 2);
            }
#pragma unroll
            for (int p = 0; p < 2; p++) {
                int row = wn * 32 + p * 16 + ((mi >> 1) << 3) + ri;
                int col = kk + ((mi & 1) << 3);
                ldsm_x4(bv[ph][p], b_base + (row * SKH + col) * 2);
            }
        }
#pragma unroll
        for (int ph = 0; ph < 2; ph++)
#pragma unroll
            for (int mt = 0; mt < 4; mt++)
#pragma unroll
                for (int nt = 0; nt < 4; nt++)
                    mma_f16(acc[mt][nt], av[ph][mt],
                            bv[ph][nt >> 1][(nt & 1) * 2], bv[ph][nt >> 1][(nt & 1) * 2 + 1]);
    }

    if (mode == 3) {
        float* C = (float*)Cv + (size_t)b * sC;
        const float* R = residual + (size_t)b * sC;
#pragma unroll
        for (int mt = 0; mt < 4; mt++) {
#pragma unroll
            for (int nt = 0; nt < 4; nt++) {
                int col = n0 + wn * 32 + nt * 8 + 2 * th4;
#pragma unroll
                for (int h = 0; h < 2; h++) {
                    int row = m0 + wm * 64 + mt * 16 + g + 8 * h;
                    float br = bias_row[row];
                    float2 rv = *(const float2*)(R + (size_t)row * ldC + col);
                    float2 o;
                    o.x = acc[mt][nt][2 * h]     + br + rv.x;
                    o.y = acc[mt][nt][2 * h + 1] + br + rv.y;
                    *(float2*)(C + (size_t)row * ldC + col) = o;
                }
            }
        }
        return;
    }

    __half* C = (__half*)Cv + (size_t)b * sC;
#pragma unroll
    for (int mt = 0; mt < 4; mt++) {
#pragma unroll
        for (int nt = 0; nt < 4; nt++) {
            int col = n0 + wn * 32 + nt * 8 + 2 * th4;
            float bc0 = bias_col ? bias_col[col]     : 0.f;
            float bc1 = bias_col ? bias_col[col + 1] : 0.f;
#pragma unroll
            for (int h = 0; h < 2; h++) {
                int row = m0 + wm * 64 + mt * 16 + g + 8 * h;
                *(__half2*)(C + (size_t)row * ldC + col) =
                    __floats2half2_rn(acc[mt][nt][2 * h] + bc0, acc[mt][nt][2 * h + 1] + bc1);
            }
        }
    }
}

// ---------------- fused attention, FA2 warp layout ---------------------------
// grid (NN/128, BB), 256 threads, 1 CTA/SM. Warp w owns queries w*16..w*16+15.
// S acc (16 queries x 128 keys per warp) -> exp in regs -> packed half2 A-
// fragments -> PV directly from registers. P never touches smem; row sums and
// normalization are warp-local.
__global__ void __launch_bounds__(256, 1)
fused_attn()
{
    extern __shared__ char smem[];

    const int tid  = threadIdx.x;
    const int lane = tid & 31;
    const int w    = tid >> 5;        // 0..7 -> query rows w*16..
    const int g    = lane >> 2;
    const int th4  = lane & 3;
    const int mi   = lane >> 3;
    const int ri   = lane & 7;

    const int m0 = blockIdx.x * 128;
    const int b  = blockIdx.y;

    const __half* qkvb = g_qkv + (size_t)b * NN * 768;
    const __half* Qg = qkvb + (size_t)m0 * 768;          // q cols 0..255
    const uint32_t su = (uint32_t)__cvta_generic_to_shared(smem);

    const int crow = tid >> 2;        // 0..63
    const int c4   = tid & 3;

    float oacc[32][4];                // 16 rows x 256 cols per warp
#pragma unroll
    for (int i = 0; i < 32; i++)
#pragma unroll
        for (int r = 0; r < 4; r++) oacc[i][r] = 0.f;
    float rsum0 = 0.f, rsum1 = 0.f;   // rows g, g+8

    auto load_k = [&](int st, int jt, int c) {
        if (jt >= NN / 128) return;
        char* sk = smem + K_OFF + st * CHUNK_B;
        const __half* Kc = qkvb + (size_t)jt * 128 * 768 + 256 + c * 32;
#pragma unroll
        for (int j = 0; j < 2; j++) {
            int row = crow + j * 64;
            cp_async16(sk + row * (SKH * 2) + c4 * 16, Kc + (size_t)row * 768 + c4 * 8);
        }
    };
    auto load_v = [&](int jt) {
        if (jt >= NN / 128) return;
        char* sv = smem + V_OFF;
        const __half* Vg = qkvb + (size_t)jt * 128 * 768 + 512;
#pragma unroll
        for (int i = 0; i < 16; i++) {
            int slot = tid + i * 256;
            int row = slot >> 5, cc = slot & 31;
            cp_async16(sv + row * (V_STRIDE * 2) + cc * 16, Vg + (size_t)row * 768 + cc * 8);
        }
    };

    // ---- prologue: Q (persistent), K0-2(0), V(0) ----
#pragma unroll
    for (int c = 0; c < 8; c++) {
        char* sq = smem + Q_OFF + c * CHUNK_B;
        const __half* Qc = Qg + c * 32;
#pragma unroll
        for (int j = 0; j < 2; j++) {
            int row = crow + j * 64;
            cp_async16(sq + row * (SKH * 2) + c4 * 16, Qc + (size_t)row * 768 + c4 * 8);
        }
    }
    cp_commit();
    load_k(0, 0, 0); cp_commit();
    load_k(1, 0, 1); cp_commit();
    load_k(2, 0, 2); cp_commit();
    load_v(0);       cp_commit();

    for (int jt = 0; jt < NN / 128; jt++) {
        float sacc[16][4];
#pragma unroll
        for (int i = 0; i < 16; i++)
#pragma unroll
            for (int r = 0; r < 4; r++) sacc[i][r] = 0.f;

        // ---- S phase: 8 K-chunks (V(jt) pinned+visible by c=3's wait+barrier)
#pragma unroll 1
        for (int c = 0; c < 8; c++) {
            if (c < 3) cp_wait<3>(); else cp_wait<2>();
            __syncthreads();
            load_k((c + 3) & 3, jt, c + 3);   // empty group for c>=5
            cp_commit();

            const uint32_t q_base = su + Q_OFF + c * CHUNK_B;
            const uint32_t k_base = su + K_OFF + (c & 3) * CHUNK_B;
#pragma unroll
            for (int ph = 0; ph < 2; ph++) {
                const int kk = ph * 16;
                uint32_t av[4], bv[8][4];
                {
                    int row = w * 16 + ((mi & 1) << 3) + ri;
                    int col = kk + ((mi & 2) << 2);
                    ldsm_x4(av, q_base + (row * SKH + col) * 2);
                }
#pragma unroll
                for (int p = 0; p < 8; p++) {
                    int row = p * 16 + ((mi >> 1) << 3) + ri;
                    int col = kk + ((mi & 1) << 3);
                    ldsm_x4(bv[p], k_base + (row * SKH + col) * 2);
                }
#pragma unroll
                for (int nt = 0; nt < 16; nt++)
                    mma_f16(sacc[nt], av,
                            bv[nt >> 1][(nt & 1) * 2], bv[nt >> 1][(nt & 1) * 2 + 1]);
            }
        }

        // prefetch next tile's first K chunks (slots 0-2 dead by barriers)
        load_k(0, jt + 1, 0); cp_commit();
        load_k(1, jt + 1, 1); cp_commit();
        load_k(2, jt + 1, 2); cp_commit();

        // ---- exp in registers -> packed A-fragments + warp-local row sums ---
        uint32_t pa[8][4];
#pragma unroll
        for (int nt = 0; nt < 16; nt++) {
            float e0 = __expf(sacc[nt][0]);
            float e1 = __expf(sacc[nt][1]);
            float e2 = __expf(sacc[nt][2]);
            float e3 = __expf(sacc[nt][3]);
            rsum0 += e0 + e1;
            rsum1 += e2 + e3;
            int ks = nt >> 1, hi = (nt & 1) * 2;
            pa[ks][hi]     = f2h2(e0, e1);   // row g
            pa[ks][hi + 1] = f2h2(e2, e3);   // row g+8
        }

        // ---- PV: O += P(regs) x V(smem, trans)  — no barrier needed --------
        {
            const uint32_t v_base = su + V_OFF;
#pragma unroll
            for (int ks = 0; ks < 8; ks++) {
                int krow = ks * 16 + ((mi & 1) << 3) + ri;
#pragma unroll
                for (int p = 0; p < 16; p++) {
                    uint32_t vb[4];
                    int colc = p * 16 + ((mi >> 1) << 3);
                    ldsm_x4_t(vb, v_base + (krow * V_STRIDE + colc) * 2);
                    mma_f16(oacc[2 * p],     pa[ks], vb[0], vb[1]);
                    mma_f16(oacc[2 * p + 1], pa[ks], vb[2], vb[3]);
                }
            }
        }
        __syncthreads();                 // all warps done reading V(jt)
        load_v(jt + 1); cp_commit();     // V(jt+1) loads under next S phase
    }

    // ---- warp-local normalization + store ----
    rsum0 += __shfl_xor_sync(0xffffffffu, rsum0, 1);
    rsum0 += __shfl_xor_sync(0xffffffffu, rsum0, 2);
    rsum1 += __shfl_xor_sync(0xffffffffu, rsum1, 1);
    rsum1 += __shfl_xor_sync(0xffffffffu, rsum1, 2);
    float inv0 = 1.f / rsum0;
    float inv1 = 1.f / rsum1;

    __half* Ob = g_at + ((size_t)b * NN + m0 + w * 16) * CC;
#pragma unroll
    for (int nt = 0; nt < 32; nt++) {
        int col = nt * 8 + 2 * th4;
        *(__half2*)(Ob + (size_t)g * CC + col) =
            __floats2half2_rn(oacc[nt][0] * inv0, oacc[nt][1] * inv0);
        *(__half2*)(Ob + (size_t)(g + 8) * CC + col) =
            __floats2half2_rn(oacc[nt][2] * inv1, oacc[nt][3] * inv1);
    }
}

// ---------------- launch -----------------------------------------------------
extern "C" void kernel_launch(void* const* d_in, const int* in_sizes, int n_in,
                              void* d_out, int out_size)
{
    const float* x     = (const float*)d_in[0];
    const float* gamma = (const float*)d_in[1];
    const float* beta  = (const float*)d_in[2];
    const float* wq    = (const float*)d_in[3];
    const float* bq    = (const float*)d_in[4];
    const float* wk    = (const float*)d_in[5];
    const float* bk    = (const float*)d_in[6];
    const float* wv    = (const float*)d_in[7];
    const float* bv    = (const float*)d_in[8];
    const float* wo    = (const float*)d_in[9];
    const float* bo    = (const float*)d_in[10];
    float* out = (float*)d_out;

    __half *wqkvh, *woh, *hn, *qkv, *at;
    float *bqkv;
    cudaGetSymbolAddress((void**)&wqkvh, g_wqkvh);
    cudaGetSymbolAddress((void**)&woh,   g_woh);
    cudaGetSymbolAddress((void**)&bqkv,  g_bqkv);
    cudaGetSymbolAddress((void**)&hn,    g_hn);
    cudaGetSymbolAddress((void**)&qkv,   g_qkv);
    cudaGetSymbolAddress((void**)&at,    g_at);

    constexpr int SMEM0 = STAGES * (TILE_A + TILE_B0);

    static bool attr_set = false;
    if (!attr_set) {
        cudaFuncSetAttribute(hgemm, cudaFuncAttributeMaxDynamicSharedMemorySize, SMEM0);
        cudaFuncSetAttribute(fused_attn, cudaFuncAttributeMaxDynamicSharedMemorySize, FUSED_SMEM);
        attr_set = true;
    }

    prep_and_stats<<<PREP_BLOCKS + BB * GG, 256>>>(wq, wk, wv, wo, bq, bk, bv, x);
    gn_transpose<<<dim3(NN / 32, CC / 32, BB), dim3(32, 8)>>>(x, gamma, beta);

    // qkv[n][768] = hn[n][c] x wqkv[d][c]^T + bqkv
    hgemm<<<dim3(768 / TBN, NN / TBM, BB), 256, SMEM0>>>(
        hn, CC, (size_t)NN * CC, wqkvh, CC, 0,
        qkv, 768, (size_t)NN * 768, CC,
        nullptr, bqkv, nullptr, 0);

    // attn = softmax(q k^T) v   (fused, FA2 warp layout)
    fused_attn<<<dim3(NN / 128, BB), 256, FUSED_SMEM>>>();

    // out[c][n] = wo[c][k] x attn[n][k]^T + bo[c] + x[c][n]   (fp32)
    hgemm<<<dim3(NN / TBN, CC / TBM, BB), 256, SMEM0>>>(
        woh, CC, 0, at, CC, (size_t)NN * CC,
        out, NN, (size_t)CC * NN, CC,
        bo, nullptr, x, 3);
}

// round 16
// speedup vs baseline: 1.1924x; 1.0065x over previous
#include <cuda_runtime.h>
#include <cuda_fp16.h>
#include <cstdint>
#include <cstddef>

#define BB   4
#define CC   256
#define NN   4096
#define GG   32
#define CPG  8
#define EPSV 1e-5f
#define SQK  0.3002806f   // sqrt(log2(e))/4 : folds 1/16 scale + log2e into q,k

#define TBM 128
#define TBN 128
#define TBK 32
#define SKH 40            // K-major smem row stride in halves (80B)
#define STAGES 4
#define TILE_A (TBM * SKH * 2)            // 10240 B
#define TILE_B0 (TBN * SKH * 2)           // 10240 B

// fused-attention smem layout (dynamic)
#define CHUNK_B 10240                      // one 128x32 panel (stride SKH)
#define Q_OFF   0                          // 8 chunks: 81920 B
#define K_OFF   (8 * CHUNK_B)              // 4 slots:  40960 B
#define V_OFF   (K_OFF + 4 * CHUNK_B)      // 122880
#define V_STRIDE 264                       // halves (528B)
#define FUSED_SMEM (V_OFF + 128 * V_STRIDE * 2)   // 190464

// ---------------- scratch (device globals) ----------------------------------
__device__ __half g_wqkvh[768 * CC];             // rows 0-255 wq*SQK, 256-511 wk*SQK, 512-767 wv
__device__ __half g_woh [CC * CC];
__device__ float  g_bqkv[768];
__device__ __half g_hn  [(size_t)BB * NN * CC];  // [b][n][c]
__device__ __half g_qkv [(size_t)BB * NN * 768]; // [b][n][768]
__device__ __half g_at  [(size_t)BB * NN * CC];  // attn [b][nq][c] (normalized)
__device__ float  g_mean[BB * GG];
__device__ float  g_rstd[BB * GG];

// ---------------- helpers ----------------------------------------------------
__device__ __forceinline__ uint32_t f2h2(float a, float b)
{
    __half2 h = __floats2half2_rn(a, b);
    return *reinterpret_cast<uint32_t*>(&h);
}
__device__ __forceinline__ uint32_t ex2h2(uint32_t x)
{
    uint32_t r;
    asm("ex2.approx.f16x2 %0, %1;" : "=r"(r) : "r"(x));
    return r;
}
__device__ __forceinline__ uint32_t hadd2u(uint32_t a, uint32_t b)
{
    __half2 ha = *reinterpret_cast<__half2*>(&a);
    __half2 hb = *reinterpret_cast<__half2*>(&b);
    __half2 hc = __hadd2(ha, hb);
    return *reinterpret_cast<uint32_t*>(&hc);
}
__device__ __forceinline__ float h2sum(uint32_t a)
{
    __half2 h = *reinterpret_cast<__half2*>(&a);
    float2 f = __half22float2(h);
    return f.x + f.y;
}
__device__ __forceinline__ void mma_f16(float* c, const uint32_t* a, uint32_t b0, uint32_t b1)
{
    asm volatile(
        "mma.sync.aligned.m16n8k16.row.col.f32.f16.f16.f32 "
        "{%0,%1,%2,%3},{%4,%5,%6,%7},{%8,%9},{%0,%1,%2,%3};\n"
        : "+f"(c[0]), "+f"(c[1]), "+f"(c[2]), "+f"(c[3])
        : "r"(a[0]), "r"(a[1]), "r"(a[2]), "r"(a[3]), "r"(b0), "r"(b1));
}
__device__ __forceinline__ void ldsm_x4(uint32_t* r, uint32_t addr)
{
    asm volatile("ldmatrix.sync.aligned.m8n8.x4.shared.b16 {%0,%1,%2,%3}, [%4];"
                 : "=r"(r[0]), "=r"(r[1]), "=r"(r[2]), "=r"(r[3]) : "r"(addr));
}
__device__ __forceinline__ void ldsm_x4_t(uint32_t* r, uint32_t addr)
{
    asm volatile("ldmatrix.sync.aligned.m8n8.x4.trans.shared.b16 {%0,%1,%2,%3}, [%4];"
                 : "=r"(r[0]), "=r"(r[1]), "=r"(r[2]), "=r"(r[3]) : "r"(addr));
}
__device__ __forceinline__ void cp_async16(void* smem_dst, const void* gptr)
{
    uint32_t s = (uint32_t)__cvta_generic_to_shared(smem_dst);
    asm volatile("cp.async.cg.shared.global [%0], [%1], 16;\n" :: "r"(s), "l"(gptr));
}
__device__ __forceinline__ void cp_commit() { asm volatile("cp.async.commit_group;\n"); }
template <int Nw>
__device__ __forceinline__ void cp_wait() { asm volatile("cp.async.wait_group %0;\n" :: "n"(Nw)); }

// ---------------- fused prep (weights->half) + groupnorm stats ---------------
#define PREP_BLOCKS 1027
__global__ void prep_and_stats(const float* __restrict__ wq, const float* __restrict__ wk,
                               const float* __restrict__ wv, const float* __restrict__ wo,
                               const float* __restrict__ bq, const float* __restrict__ bk,
                               const float* __restrict__ bv, const float* __restrict__ x)
{
    if (blockIdx.x < PREP_BLOCKS) {
        int i = blockIdx.x * 256 + threadIdx.x;
        if (i < 196608) {
            int r = i >> 8;
            float v;
            if (r < 256)      v = wq[i] * SQK;
            else if (r < 512) v = wk[i - 65536] * SQK;
            else              v = wv[i - 131072];
            g_wqkvh[i] = __float2half(v);
        } else if (i < 262144) {
            g_woh[i - 196608] = __float2half(wo[i - 196608]);
        } else if (i < 262912) {
            int j = i - 262144;
            float v;
            if (j < 256)      v = bq[j] * SQK;
            else if (j < 512) v = bk[j - 256] * SQK;
            else              v = bv[j - 512];
            g_bqkv[j] = v;
        }
        return;
    }
    int bg = blockIdx.x - PREP_BLOCKS;
    const float* xs = x + (size_t)bg * (CPG * NN);
    float s = 0.f, s2 = 0.f;
    for (int i = threadIdx.x; i < CPG * NN; i += 256) {
        float v = xs[i];
        s += v; s2 += v * v;
    }
    __shared__ float rs[512];
    rs[threadIdx.x] = s; rs[256 + threadIdx.x] = s2;
    __syncthreads();
    for (int off = 128; off > 0; off >>= 1) {
        if (threadIdx.x < off) {
            rs[threadIdx.x]       += rs[threadIdx.x + off];
            rs[256 + threadIdx.x] += rs[256 + threadIdx.x + off];
        }
        __syncthreads();
    }
    if (threadIdx.x == 0) {
        float mean = rs[0] * (1.f / (CPG * NN));
        float var  = rs[256] * (1.f / (CPG * NN)) - mean * mean;
        g_mean[bg] = mean;
        g_rstd[bg] = rsqrtf(var + EPSV);
    }
}

// x[b][c][n] -> hn[b][n][c] (half)
__global__ void gn_transpose(const float* __restrict__ x,
                             const float* __restrict__ gamma, const float* __restrict__ beta)
{
    __shared__ float tile[32][33];
    int b = blockIdx.z;
    int n0 = blockIdx.x * 32, c0 = blockIdx.y * 32;
    int tx = threadIdx.x, ty = threadIdx.y;
    const float* xb = x + (size_t)b * CC * NN;
#pragma unroll
    for (int j = 0; j < 4; j++) {
        int c = c0 + ty + j * 8;
        float mean = g_mean[b * GG + (c >> 3)];
        float rstd = g_rstd[b * GG + (c >> 3)];
        float ga = gamma[c] * rstd;
        float be = beta[c] - mean * ga;
        tile[ty + j * 8][tx] = xb[(size_t)c * NN + n0 + tx] * ga + be;
    }
    __syncthreads();
    __half* hb = g_hn + (size_t)b * NN * CC;
#pragma unroll
    for (int j = 0; j < 4; j++) {
        int n = n0 + ty + j * 8;
        hb[(size_t)n * CC + c0 + tx] = __float2half(tile[tx][ty + j * 8]);
    }
}

// ---------------- fp16 TC GEMM (R10 proven; modes 0 and 3) -------------------
__global__ void __launch_bounds__(256, 2)
hgemm(const __half* __restrict__ A, int ldA, size_t sA,
      const __half* __restrict__ B, int ldB, size_t sB,
      void* __restrict__ Cv, int ldC, size_t sC,
      int K,
      const float* __restrict__ bias_row, const float* __restrict__ bias_col,
      const float* __restrict__ residual, int mode)
{
    constexpr int STAGE_B = TILE_A + TILE_B0;
    const int b  = blockIdx.z;
    const int m0 = blockIdx.y * TBM;
    const int n0 = blockIdx.x * TBN;

    extern __shared__ char smem[];

    const int tid  = threadIdx.x;
    const int lane = tid & 31;
    const int wid  = tid >> 5;
    const int wm   = wid >> 2;
    const int wn   = wid & 3;
    const int g    = lane >> 2;
    const int th4  = lane & 3;
    const int mi   = lane >> 3;
    const int ri   = lane & 7;

    const __half* Ap = A + (size_t)b * sA + (size_t)m0 * ldA;
    const __half* Bp = B + (size_t)b * sB + (size_t)n0 * ldB;
    const uint32_t su = (uint32_t)__cvta_generic_to_shared(smem);

    float acc[4][4][4];
#pragma unroll
    for (int i = 0; i < 4; i++)
#pragma unroll
        for (int j = 0; j < 4; j++)
#pragma unroll
            for (int r = 0; r < 4; r++) acc[i][j][r] = 0.f;

    const int T = K / TBK;
    const int crow = tid >> 2;
    const int c4   = tid & 3;

    auto load_tile = [&](int st, int t) {
        char* sa = smem + st * STAGE_B;
        char* sb = sa + TILE_A;
        const __half* Ag = Ap + (size_t)t * TBK;
        const __half* Bg = Bp + (size_t)t * TBK;
#pragma unroll
        for (int j = 0; j < 2; j++) {
            int row = crow + j * 64;
            cp_async16(sa + row * (SKH * 2) + c4 * 16, Ag + (size_t)row * ldA + c4 * 8);
            cp_async16(sb + row * (SKH * 2) + c4 * 16, Bg + (size_t)row * ldB + c4 * 8);
        }
    };

#pragma unroll
    for (int t = 0; t < STAGES - 1; t++) {
        if (t < T) load_tile(t, t);
        cp_commit();
    }

    for (int t = 0; t < T; t++) {
        cp_wait<STAGES - 2>();
        __syncthreads();
        int tl = t + STAGES - 1;
        if (tl < T) load_tile(tl % STAGES, tl);
        cp_commit();

        const int slot = t % STAGES;
        const uint32_t a_base = su + slot * STAGE_B;
        const uint32_t b_base = a_base + TILE_A;

        uint32_t av[2][4][4], bv[2][2][4];
#pragma unroll
        for (int ph = 0; ph < 2; ph++) {
            const int kk = ph * 16;
#pragma unroll
            for (int mt = 0; mt < 4; mt++) {
                int row = wm * 64 + mt * 16 + ((mi & 1) << 3) + ri;
                int col = kk + ((mi & 2) << 2);
                ldsm_x4(av[ph][mt], a_base + (row * SKH + col) * 2);
            }
#pragma unroll
            for (int p = 0; p < 2; p++) {
                int row = wn * 32 + p * 16 + ((mi >> 1) << 3) + ri;
                int col = kk + ((mi & 1) << 3);
                ldsm_x4(bv[ph][p], b_base + (row * SKH + col) * 2);
            }
        }
#pragma unroll
        for (int ph = 0; ph < 2; ph++)
#pragma unroll
            for (int mt = 0; mt < 4; mt++)
#pragma unroll
                for (int nt = 0; nt < 4; nt++)
                    mma_f16(acc[mt][nt], av[ph][mt],
                            bv[ph][nt >> 1][(nt & 1) * 2], bv[ph][nt >> 1][(nt & 1) * 2 + 1]);
    }

    if (mode == 3) {
        float* C = (float*)Cv + (size_t)b * sC;
        const float* R = residual + (size_t)b * sC;
#pragma unroll
        for (int mt = 0; mt < 4; mt++) {
#pragma unroll
            for (int nt = 0; nt < 4; nt++) {
                int col = n0 + wn * 32 + nt * 8 + 2 * th4;
#pragma unroll
                for (int h = 0; h < 2; h++) {
                    int row = m0 + wm * 64 + mt * 16 + g + 8 * h;
                    float br = bias_row[row];
                    float2 rv = *(const float2*)(R + (size_t)row * ldC + col);
                    float2 o;
                    o.x = acc[mt][nt][2 * h]     + br + rv.x;
                    o.y = acc[mt][nt][2 * h + 1] + br + rv.y;
                    *(float2*)(C + (size_t)row * ldC + col) = o;
                }
            }
        }
        return;
    }

    __half* C = (__half*)Cv + (size_t)b * sC;
#pragma unroll
    for (int mt = 0; mt < 4; mt++) {
#pragma unroll
        for (int nt = 0; nt < 4; nt++) {
            int col = n0 + wn * 32 + nt * 8 + 2 * th4;
            float bc0 = bias_col ? bias_col[col]     : 0.f;
            float bc1 = bias_col ? bias_col[col + 1] : 0.f;
#pragma unroll
            for (int h = 0; h < 2; h++) {
                int row = m0 + wm * 64 + mt * 16 + g + 8 * h;
                *(__half2*)(C + (size_t)row * ldC + col) =
                    __floats2half2_rn(acc[mt][nt][2 * h] + bc0, acc[mt][nt][2 * h + 1] + bc1);
            }
        }
    }
}

// ---------------- fused attention, FA2 warp layout, ex2.f16x2 softmax --------
__global__ void __launch_bounds__(256, 1)
fused_attn()
{
    extern __shared__ char smem[];

    const int tid  = threadIdx.x;
    const int lane = tid & 31;
    const int w    = tid >> 5;        // 0..7 -> query rows w*16..
    const int g    = lane >> 2;
    const int th4  = lane & 3;
    const int mi   = lane >> 3;
    const int ri   = lane & 7;

    const int m0 = blockIdx.x * 128;
    const int b  = blockIdx.y;

    const __half* qkvb = g_qkv + (size_t)b * NN * 768;
    const __half* Qg = qkvb + (size_t)m0 * 768;          // q cols 0..255
    const uint32_t su = (uint32_t)__cvta_generic_to_shared(smem);

    const int crow = tid >> 2;        // 0..63
    const int c4   = tid & 3;

    float oacc[32][4];                // 16 rows x 256 cols per warp
#pragma unroll
    for (int i = 0; i < 32; i++)
#pragma unroll
        for (int r = 0; r < 4; r++) oacc[i][r] = 0.f;
    float rsum0 = 0.f, rsum1 = 0.f;   // rows g, g+8

    auto load_k = [&](int st, int jt, int c) {
        if (jt >= NN / 128) return;
        char* sk = smem + K_OFF + st * CHUNK_B;
        const __half* Kc = qkvb + (size_t)jt * 128 * 768 + 256 + c * 32;
#pragma unroll
        for (int j = 0; j < 2; j++) {
            int row = crow + j * 64;
            cp_async16(sk + row * (SKH * 2) + c4 * 16, Kc + (size_t)row * 768 + c4 * 8);
        }
    };
    auto load_v = [&](int jt) {
        if (jt >= NN / 128) return;
        char* sv = smem + V_OFF;
        const __half* Vg = qkvb + (size_t)jt * 128 * 768 + 512;
#pragma unroll
        for (int i = 0; i < 16; i++) {
            int slot = tid + i * 256;
            int row = slot >> 5, cc = slot & 31;
            cp_async16(sv + row * (V_STRIDE * 2) + cc * 16, Vg + (size_t)row * 768 + cc * 8);
        }
    };

    // ---- prologue: Q (persistent), K0-2(0), V(0) ----
#pragma unroll
    for (int c = 0; c < 8; c++) {
        char* sq = smem + Q_OFF + c * CHUNK_B;
        const __half* Qc = Qg + c * 32;
#pragma unroll
        for (int j = 0; j < 2; j++) {
            int row = crow + j * 64;
            cp_async16(sq + row * (SKH * 2) + c4 * 16, Qc + (size_t)row * 768 + c4 * 8);
        }
    }
    cp_commit();
    load_k(0, 0, 0); cp_commit();
    load_k(1, 0, 1); cp_commit();
    load_k(2, 0, 2); cp_commit();
    load_v(0);       cp_commit();

    for (int jt = 0; jt < NN / 128; jt++) {
        float sacc[16][4];
#pragma unroll
        for (int i = 0; i < 16; i++)
#pragma unroll
            for (int r = 0; r < 4; r++) sacc[i][r] = 0.f;

        // ---- S phase: 8 K-chunks ----
#pragma unroll 1
        for (int c = 0; c < 8; c++) {
            if (c < 3) cp_wait<3>(); else cp_wait<2>();
            __syncthreads();
            load_k((c + 3) & 3, jt, c + 3);   // empty group for c>=5
            cp_commit();

            const uint32_t q_base = su + Q_OFF + c * CHUNK_B;
            const uint32_t k_base = su + K_OFF + (c & 3) * CHUNK_B;
#pragma unroll
            for (int ph = 0; ph < 2; ph++) {
                const int kk = ph * 16;
                uint32_t av[4], bv[8][4];
                {
                    int row = w * 16 + ((mi & 1) << 3) + ri;
                    int col = kk + ((mi & 2) << 2);
                    ldsm_x4(av, q_base + (row * SKH + col) * 2);
                }
#pragma unroll
                for (int p = 0; p < 8; p++) {
                    int row = p * 16 + ((mi >> 1) << 3) + ri;
                    int col = kk + ((mi & 1) << 3);
                    ldsm_x4(bv[p], k_base + (row * SKH + col) * 2);
                }
#pragma unroll
                for (int nt = 0; nt < 16; nt++)
                    mma_f16(sacc[nt], av,
                            bv[nt >> 1][(nt & 1) * 2], bv[nt >> 1][(nt & 1) * 2 + 1]);
            }
        }

        // prefetch next tile's first K chunks (slots 0-2 dead by barriers)
        load_k(0, jt + 1, 0); cp_commit();
        load_k(1, jt + 1, 1); cp_commit();
        load_k(2, jt + 1, 2); cp_commit();

        // ---- softmax: half2 ex2 in registers -> A-fragments + row sums ------
        uint32_t pa[8][4];
        uint32_t rs0 = 0, rs1 = 0;        // half2 accumulators (rows g, g+8)
#pragma unroll
        for (int nt = 0; nt < 16; nt++) {
            int ks = nt >> 1, hi = (nt & 1) * 2;
            uint32_t e01 = ex2h2(f2h2(sacc[nt][0], sacc[nt][1]));  // row g
            uint32_t e23 = ex2h2(f2h2(sacc[nt][2], sacc[nt][3]));  // row g+8
            pa[ks][hi]     = e01;
            pa[ks][hi + 1] = e23;
            rs0 = hadd2u(rs0, e01);
            rs1 = hadd2u(rs1, e23);
        }
        rsum0 += h2sum(rs0);
        rsum1 += h2sum(rs1);

        // ---- PV: O += P(regs) x V(smem, trans) ------------------------------
        {
            const uint32_t v_base = su + V_OFF;
#pragma unroll
            for (int ks = 0; ks < 8; ks++) {
                int krow = ks * 16 + ((mi & 1) << 3) + ri;
#pragma unroll
                for (int p = 0; p < 16; p++) {
                    uint32_t vb[4];
                    int colc = p * 16 + ((mi >> 1) << 3);
                    ldsm_x4_t(vb, v_base + (krow * V_STRIDE + colc) * 2);
                    mma_f16(oacc[2 * p],     pa[ks], vb[0], vb[1]);
                    mma_f16(oacc[2 * p + 1], pa[ks], vb[2], vb[3]);
                }
            }
        }
        __syncthreads();                 // all warps done reading V(jt)
        load_v(jt + 1); cp_commit();     // V(jt+1) loads under next S phase
    }

    // ---- warp-local normalization + store ----
    rsum0 += __shfl_xor_sync(0xffffffffu, rsum0, 1);
    rsum0 += __shfl_xor_sync(0xffffffffu, rsum0, 2);
    rsum1 += __shfl_xor_sync(0xffffffffu, rsum1, 1);
    rsum1 += __shfl_xor_sync(0xffffffffu, rsum1, 2);
    float inv0 = 1.f / rsum0;
    float inv1 = 1.f / rsum1;

    __half* Ob = g_at + ((size_t)b * NN + m0 + w * 16) * CC;
#pragma unroll
    for (int nt = 0; nt < 32; nt++) {
        int col = nt * 8 + 2 * th4;
        *(__half2*)(Ob + (size_t)g * CC + col) =
            __floats2half2_rn(oacc[nt][0] * inv0, oacc[nt][1] * inv0);
        *(__half2*)(Ob + (size_t)(g + 8) * CC + col) =
            __floats2half2_rn(oacc[nt][2] * inv1, oacc[nt][3] * inv1);
    }
}

// ---------------- launch -----------------------------------------------------
extern "C" void kernel_launch(void* const* d_in, const int* in_sizes, int n_in,
                              void* d_out, int out_size)
{
    const float* x     = (const float*)d_in[0];
    const float* gamma = (const float*)d_in[1];
    const float* beta  = (const float*)d_in[2];
    const float* wq    = (const float*)d_in[3];
    const float* bq    = (const float*)d_in[4];
    const float* wk    = (const float*)d_in[5];
    const float* bk    = (const float*)d_in[6];
    const float* wv    = (const float*)d_in[7];
    const float* bv    = (const float*)d_in[8];
    const float* wo    = (const float*)d_in[9];
    const float* bo    = (const float*)d_in[10];
    float* out = (float*)d_out;

    __half *wqkvh, *woh, *hn, *qkv, *at;
    float *bqkv;
    cudaGetSymbolAddress((void**)&wqkvh, g_wqkvh);
    cudaGetSymbolAddress((void**)&woh,   g_woh);
    cudaGetSymbolAddress((void**)&bqkv,  g_bqkv);
    cudaGetSymbolAddress((void**)&hn,    g_hn);
    cudaGetSymbolAddress((void**)&qkv,   g_qkv);
    cudaGetSymbolAddress((void**)&at,    g_at);

    constexpr int SMEM0 = STAGES * (TILE_A + TILE_B0);

    static bool attr_set = false;
    if (!attr_set) {
        cudaFuncSetAttribute(hgemm, cudaFuncAttributeMaxDynamicSharedMemorySize, SMEM0);
        cudaFuncSetAttribute(fused_attn, cudaFuncAttributeMaxDynamicSharedMemorySize, FUSED_SMEM);
        attr_set = true;
    }

    prep_and_stats<<<PREP_BLOCKS + BB * GG, 256>>>(wq, wk, wv, wo, bq, bk, bv, x);
    gn_transpose<<<dim3(NN / 32, CC / 32, BB), dim3(32, 8)>>>(x, gamma, beta);

    // qkv[n][768] = hn[n][c] x wqkv[d][c]^T + bqkv
    hgemm<<<dim3(768 / TBN, NN / TBM, BB), 256, SMEM0>>>(
        hn, CC, (size_t)NN * CC, wqkvh, CC, 0,
        qkv, 768, (size_t)NN * 768, CC,
        nullptr, bqkv, nullptr, 0);

    // attn = softmax(q k^T) v   (fused, FA2 layout, ex2.f16x2)
    fused_attn<<<dim3(NN / 128, BB), 256, FUSED_SMEM>>>();

    // out[c][n] = wo[c][k] x attn[n][k]^T + bo[c] + x[c][n]   (fp32)
    hgemm<<<dim3(NN / TBN, CC / TBM, BB), 256, SMEM0>>>(
        woh, CC, 0, at, CC, (size_t)NN * CC,
        out, NN, (size_t)CC * NN, CC,
        bo, nullptr, x, 3);
}